// round 1
// baseline (speedup 1.0000x reference)
#include <cuda_runtime.h>
#include <math.h>

#define BATCH  2
#define SEQ    2048
#define DMODEL 2048
#define NHEAD  16
#define NKV    4
#define HDIM   128
#define KVDIM  1024          // 2*NKV*HDIM
#define MTOT   4096          // BATCH*SEQ

// Scratch (device globals: allocation-free per harness rules)
__device__ float g_q [(size_t)MTOT * DMODEL];   // [B,T,H,d]
__device__ float g_kv[(size_t)MTOT * KVDIM];    // [B,T, (k:4*128 | v:4*128)]
__device__ float g_y [(size_t)MTOT * DMODEL];   // [B,T,H,d]

// ---------------------------------------------------------------------------
// NT GEMM: C[m,n] = sum_k A[m,k] * B[n,k]   (A: MxK row-major, B: NxK row-major)
// BM=BN=128, BK=16, 256 threads, 8x8 micro-tile.
// ---------------------------------------------------------------------------
#define GBM 128
#define GBN 128
#define GBK 16
#define GPAD 132   // smem row stride (floats); 132*4B % 16 == 0 (float4-aligned)

__global__ __launch_bounds__(256, 2)
void gemm_nt(const float* __restrict__ A, const float* __restrict__ B,
             float* __restrict__ C, int M, int N, int K)
{
    __shared__ float As[GBK][GPAD];
    __shared__ float Bs[GBK][GPAD];

    const int tid   = threadIdx.x;
    const int mbase = blockIdx.y * GBM;
    const int nbase = blockIdx.x * GBN;
    const int ty = tid >> 4;      // 0..15
    const int tx = tid & 15;      // 0..15

    float acc[8][8] = {};

    for (int kb = 0; kb < K; kb += GBK) {
        // Load A,B tiles: 128 rows x 16 cols = 512 float4 each; 2 per thread.
        #pragma unroll
        for (int i = 0; i < 2; i++) {
            int s   = tid + i * 256;          // 0..511
            int row = s >> 2;
            int c4  = (s & 3) << 2;
            float4 a = *(const float4*)&A[(size_t)(mbase + row) * K + kb + c4];
            As[c4 + 0][row] = a.x; As[c4 + 1][row] = a.y;
            As[c4 + 2][row] = a.z; As[c4 + 3][row] = a.w;
            float4 b = *(const float4*)&B[(size_t)(nbase + row) * K + kb + c4];
            Bs[c4 + 0][row] = b.x; Bs[c4 + 1][row] = b.y;
            Bs[c4 + 2][row] = b.z; Bs[c4 + 3][row] = b.w;
        }
        __syncthreads();

        #pragma unroll
        for (int k = 0; k < GBK; k++) {
            float a[8], b[8];
            *(float4*)&a[0] = *(const float4*)&As[k][ty * 8];
            *(float4*)&a[4] = *(const float4*)&As[k][ty * 8 + 4];
            *(float4*)&b[0] = *(const float4*)&Bs[k][tx * 8];
            *(float4*)&b[4] = *(const float4*)&Bs[k][tx * 8 + 4];
            #pragma unroll
            for (int i = 0; i < 8; i++)
                #pragma unroll
                for (int j = 0; j < 8; j++)
                    acc[i][j] = fmaf(a[i], b[j], acc[i][j]);
        }
        __syncthreads();
    }

    #pragma unroll
    for (int i = 0; i < 8; i++) {
        int m = mbase + ty * 8 + i;
        #pragma unroll
        for (int j = 0; j < 8; j += 4) {
            float4 v = make_float4(acc[i][j], acc[i][j+1], acc[i][j+2], acc[i][j+3]);
            *(float4*)&C[(size_t)m * N + nbase + tx * 8 + j] = v;
        }
    }
}

// ---------------------------------------------------------------------------
// RoPE (rotate-half, non-adjacent pairs), applied in place.
// buf layout: [MTOT][rowstride], head h at column h*HDIM.
// out[j]    = x[j]*cos - x[j+64]*sin
// out[j+64] = x[j+64]*cos + x[j]*sin ,  angle = t / base^(j/64)
// ---------------------------------------------------------------------------
__global__ void rope_kernel(float* __restrict__ buf, int rowstride, int nheads)
{
    int idx = blockIdx.x * blockDim.x + threadIdx.x;
    int total = MTOT * nheads * (HDIM / 2);
    if (idx >= total) return;

    int j = idx & 63;
    int h = (idx >> 6) % nheads;
    int m = idx / (64 * nheads);
    int t = m & (SEQ - 1);

    float freq = powf(10000.0f, (float)j * (1.0f / 64.0f));
    float ang  = (float)t / freq;
    float s, c;
    sincosf(ang, &s, &c);

    float* p = buf + (size_t)m * rowstride + h * HDIM;
    float x1 = p[j];
    float x2 = p[j + 64];
    p[j]      = x1 * c - x2 * s;
    p[j + 64] = x2 * c + x1 * s;
}

// ---------------------------------------------------------------------------
// Flash attention, fp32, causal, GQA (4 q-heads per kv-head).
// Block: 256 threads, 64 queries x 64 keys per tile, d = 128.
// smem: sQ[64][132], sKT[128][68] (K transposed), sV[64][132], sS[64][68],
//       rowm/rowl/rowa[64].
// ---------------------------------------------------------------------------
#define FBM 64
#define FBN 64
#define QPAD 132
#define KTPAD 68
#define SPAD 68

#define SM_Q   0
#define SM_KT  (SM_Q  + FBM * QPAD)          // 8448
#define SM_V   (SM_KT + HDIM * KTPAD)        // + 8704
#define SM_S   (SM_V  + FBM * QPAD)          // + 8448
#define SM_RM  (SM_S  + FBM * SPAD)          // + 4352
#define SM_RL  (SM_RM + FBM)
#define SM_RA  (SM_RL + FBM)
#define SM_TOTAL_FLOATS (SM_RA + FBM)

__global__ __launch_bounds__(256, 1)
void attn_kernel(const float* __restrict__ Q, const float* __restrict__ KV,
                 float* __restrict__ Y)
{
    extern __shared__ float sm[];
    float* sQ   = sm + SM_Q;
    float* sKT  = sm + SM_KT;
    float* sV   = sm + SM_V;
    float* sS   = sm + SM_S;
    float* rowm = sm + SM_RM;
    float* rowl = sm + SM_RL;
    float* rowa = sm + SM_RA;

    const int tid   = threadIdx.x;
    const int qtile = blockIdx.x;
    const int bh    = blockIdx.y;
    const int b     = bh >> 4;
    const int h     = bh & 15;
    const int kvh   = h >> 2;
    const int qbase = qtile * FBM;

    const float* Qp = Q  + ((size_t)(b * SEQ + qbase)) * DMODEL + h * HDIM;
    const float* Kp = KV + ((size_t)(b * SEQ)) * KVDIM + kvh * HDIM;
    const float* Vp = Kp + NKV * HDIM;   // V block starts 512 floats later

    // Load Q tile: 64x128 = 2048 float4; 8 per thread
    #pragma unroll
    for (int i = 0; i < 8; i++) {
        int s   = tid + i * 256;
        int row = s >> 5;
        int c4  = (s & 31) << 2;
        float4 v = *(const float4*)&Qp[(size_t)row * DMODEL + c4];
        *(float4*)&sQ[row * QPAD + c4] = v;
    }
    if (tid < FBM) { rowm[tid] = -INFINITY; rowl[tid] = 0.0f; }

    float acc[4][8] = {};
    const int sy = tid >> 4;   // 0..15 (row group of 4)
    const int sx = tid & 15;   // 0..15
    __syncthreads();

    const float scale = 0.08838834764831845f;   // 1/sqrt(128)

    for (int kt = 0; kt <= qtile; kt++) {
        const int kbase = kt * FBN;

        // Load K (transposed into sKT[d][n]) and V (natural)
        #pragma unroll
        for (int i = 0; i < 8; i++) {
            int s   = tid + i * 256;
            int row = s >> 5;
            int c4  = (s & 31) << 2;
            float4 kv4 = *(const float4*)&Kp[(size_t)(kbase + row) * KVDIM + c4];
            sKT[(c4 + 0) * KTPAD + row] = kv4.x;
            sKT[(c4 + 1) * KTPAD + row] = kv4.y;
            sKT[(c4 + 2) * KTPAD + row] = kv4.z;
            sKT[(c4 + 3) * KTPAD + row] = kv4.w;
            float4 vv = *(const float4*)&Vp[(size_t)(kbase + row) * KVDIM + c4];
            *(float4*)&sV[row * QPAD + c4] = vv;
        }
        __syncthreads();

        // S = Q K^T (4x4 micro-tile per thread)
        float sacc[4][4] = {};
        #pragma unroll 4
        for (int k = 0; k < HDIM; k++) {
            float4 kf = *(const float4*)&sKT[k * KTPAD + sx * 4];
            float kq[4] = {kf.x, kf.y, kf.z, kf.w};
            #pragma unroll
            for (int i = 0; i < 4; i++) {
                float qv = sQ[(sy * 4 + i) * QPAD + k];
                #pragma unroll
                for (int j = 0; j < 4; j++)
                    sacc[i][j] = fmaf(qv, kq[j], sacc[i][j]);
            }
        }
        // scale + causal mask, write to sS
        #pragma unroll
        for (int i = 0; i < 4; i++) {
            int qpos = qbase + sy * 4 + i;
            #pragma unroll
            for (int j = 0; j < 4; j++) {
                int kpos = kbase + sx * 4 + j;
                float v = (kpos <= qpos) ? sacc[i][j] * scale : -1e30f;
                sS[(sy * 4 + i) * SPAD + sx * 4 + j] = v;
            }
        }
        __syncthreads();

        // Online softmax per row (one thread per row)
        if (tid < FBM) {
            float m_old = rowm[tid];
            float mx = m_old;
            float* srow = &sS[tid * SPAD];
            #pragma unroll 8
            for (int c = 0; c < FBN; c++) mx = fmaxf(mx, srow[c]);
            float sum = 0.0f;
            #pragma unroll 8
            for (int c = 0; c < FBN; c++) {
                float p = __expf(srow[c] - mx);
                srow[c] = p;
                sum += p;
            }
            float alpha = __expf(m_old - mx);   // 0 on first tile (m_old=-inf)
            rowl[tid] = rowl[tid] * alpha + sum;
            rowm[tid] = mx;
            rowa[tid] = alpha;
        }
        __syncthreads();

        // O = O*alpha + P @ V  (4 rows x 8 cols per thread)
        {
            #pragma unroll
            for (int i = 0; i < 4; i++) {
                float al = rowa[sy * 4 + i];
                #pragma unroll
                for (int j = 0; j < 8; j++) acc[i][j] *= al;
            }
            #pragma unroll 2
            for (int kk = 0; kk < FBN; kk++) {
                float4 v0 = *(const float4*)&sV[kk * QPAD + sx * 8];
                float4 v1 = *(const float4*)&sV[kk * QPAD + sx * 8 + 4];
                float vv[8] = {v0.x, v0.y, v0.z, v0.w, v1.x, v1.y, v1.z, v1.w};
                #pragma unroll
                for (int i = 0; i < 4; i++) {
                    float p = sS[(sy * 4 + i) * SPAD + kk];
                    #pragma unroll
                    for (int j = 0; j < 8; j++)
                        acc[i][j] = fmaf(p, vv[j], acc[i][j]);
                }
            }
        }
        __syncthreads();   // protect sKT/sV before next tile's load
    }

    // Epilogue: normalize and write out [B,T,H,d]
    float* Yp = Y + ((size_t)(b * SEQ + qbase)) * DMODEL + h * HDIM;
    #pragma unroll
    for (int i = 0; i < 4; i++) {
        int r = sy * 4 + i;
        float inv = 1.0f / rowl[r];
        float4 o0 = make_float4(acc[i][0] * inv, acc[i][1] * inv,
                                acc[i][2] * inv, acc[i][3] * inv);
        float4 o1 = make_float4(acc[i][4] * inv, acc[i][5] * inv,
                                acc[i][6] * inv, acc[i][7] * inv);
        *(float4*)&Yp[(size_t)r * DMODEL + sx * 8]     = o0;
        *(float4*)&Yp[(size_t)r * DMODEL + sx * 8 + 4] = o1;
    }
}

// ---------------------------------------------------------------------------
extern "C" void kernel_launch(void* const* d_in, const int* in_sizes, int n_in,
                              void* d_out, int out_size)
{
    (void)in_sizes; (void)n_in; (void)out_size;
    const float* x     = (const float*)d_in[0];
    const float* Wq    = (const float*)d_in[1];
    const float* Wkv   = (const float*)d_in[2];
    const float* Wproj = (const float*)d_in[3];
    float* out = (float*)d_out;

    float *q_ptr, *kv_ptr, *y_ptr;
    cudaGetSymbolAddress((void**)&q_ptr,  g_q);
    cudaGetSymbolAddress((void**)&kv_ptr, g_kv);
    cudaGetSymbolAddress((void**)&y_ptr,  g_y);

    // 1) Q = x @ Wq^T   [4096,2048]
    gemm_nt<<<dim3(DMODEL / GBN, MTOT / GBM), 256>>>(x, Wq, q_ptr, MTOT, DMODEL, DMODEL);
    // 2) KV = x @ Wkv^T [4096,1024]
    gemm_nt<<<dim3(KVDIM / GBN, MTOT / GBM), 256>>>(x, Wkv, kv_ptr, MTOT, KVDIM, DMODEL);

    // 3) RoPE on q (16 heads) and k (first 4 head-blocks of kv)
    {
        int total_q = MTOT * NHEAD * (HDIM / 2);
        rope_kernel<<<(total_q + 255) / 256, 256>>>(q_ptr, DMODEL, NHEAD);
        int total_k = MTOT * NKV * (HDIM / 2);
        rope_kernel<<<(total_k + 255) / 256, 256>>>(kv_ptr, KVDIM, NKV);
    }

    // 4) Causal GQA flash attention -> y [B,T,H,d]
    {
        size_t smem = (size_t)SM_TOTAL_FLOATS * sizeof(float);
        cudaFuncSetAttribute(attn_kernel, cudaFuncAttributeMaxDynamicSharedMemorySize,
                             (int)smem);
        attn_kernel<<<dim3(SEQ / FBM, BATCH * NHEAD), 256, smem>>>(q_ptr, kv_ptr, y_ptr);
    }

    // 5) out = y @ Wproj^T
    gemm_nt<<<dim3(DMODEL / GBN, MTOT / GBM), 256>>>(y_ptr, Wproj, out, MTOT, DMODEL, DMODEL);
}

// round 3
// speedup vs baseline: 2.9376x; 2.9376x over previous
#include <cuda_runtime.h>
#include <cuda_bf16.h>
#include <cstdint>
#include <math.h>

#define BATCH  2
#define SEQ    2048
#define DMODEL 2048
#define NHEAD  16
#define NKV    4
#define HDIM   128
#define KVDIM  1024
#define MTOT   4096

// ---------------- scratch ----------------
__device__ float g_q [(size_t)MTOT * DMODEL];
__device__ float g_kv[(size_t)MTOT * KVDIM];

__device__ __nv_bfloat16 g_xh [(size_t)MTOT * DMODEL];
__device__ __nv_bfloat16 g_xl [(size_t)MTOT * DMODEL];
__device__ __nv_bfloat16 g_wqh[(size_t)DMODEL * DMODEL];
__device__ __nv_bfloat16 g_wql[(size_t)DMODEL * DMODEL];
__device__ __nv_bfloat16 g_wkh[(size_t)KVDIM * DMODEL];
__device__ __nv_bfloat16 g_wkl[(size_t)KVDIM * DMODEL];
__device__ __nv_bfloat16 g_wph[(size_t)DMODEL * DMODEL];
__device__ __nv_bfloat16 g_wpl[(size_t)DMODEL * DMODEL];
__device__ __nv_bfloat16 g_qh [(size_t)MTOT * DMODEL];
__device__ __nv_bfloat16 g_ql [(size_t)MTOT * DMODEL];
__device__ __nv_bfloat16 g_kvh[(size_t)MTOT * KVDIM];
__device__ __nv_bfloat16 g_kvl[(size_t)MTOT * KVDIM];
__device__ __nv_bfloat16 g_yh [(size_t)MTOT * DMODEL];
__device__ __nv_bfloat16 g_yl [(size_t)MTOT * DMODEL];

// ---------------- helpers ----------------
__device__ __forceinline__ uint32_t smem_u32(const void* p) {
    uint32_t a;
    asm("{ .reg .u64 t; cvta.to.shared.u64 t, %1; cvt.u32.u64 %0, t; }" : "=r"(a) : "l"(p));
    return a;
}
__device__ __forceinline__ void ldsm_x4(uint32_t* r, uint32_t addr) {
    asm volatile("ldmatrix.sync.aligned.m8n8.x4.shared.b16 {%0,%1,%2,%3}, [%4];"
                 : "=r"(r[0]), "=r"(r[1]), "=r"(r[2]), "=r"(r[3]) : "r"(addr));
}
__device__ __forceinline__ void ldsm_x4_t(uint32_t* r, uint32_t addr) {
    asm volatile("ldmatrix.sync.aligned.m8n8.x4.trans.shared.b16 {%0,%1,%2,%3}, [%4];"
                 : "=r"(r[0]), "=r"(r[1]), "=r"(r[2]), "=r"(r[3]) : "r"(addr));
}
__device__ __forceinline__ void mma_bf16(float* d, const uint32_t* a, const uint32_t* b) {
    asm volatile(
        "mma.sync.aligned.m16n8k16.row.col.f32.bf16.bf16.f32 "
        "{%0,%1,%2,%3}, {%4,%5,%6,%7}, {%8,%9}, {%0,%1,%2,%3};"
        : "+f"(d[0]), "+f"(d[1]), "+f"(d[2]), "+f"(d[3])
        : "r"(a[0]), "r"(a[1]), "r"(a[2]), "r"(a[3]), "r"(b[0]), "r"(b[1]));
}
__device__ __forceinline__ uint32_t bf2_as_u32(__nv_bfloat162 v) {
    return *reinterpret_cast<uint32_t*>(&v);
}

// ---------------- fp32 -> bf16 hi/lo split ----------------
__global__ void split_kernel(const float* __restrict__ src,
                             __nv_bfloat16* __restrict__ hi,
                             __nv_bfloat16* __restrict__ lo, int n4)
{
    int i = blockIdx.x * blockDim.x + threadIdx.x;
    if (i >= n4) return;
    float4 v = ((const float4*)src)[i];
    float vs[4] = {v.x, v.y, v.z, v.w};
    union { __nv_bfloat16 b[4]; uint2 u; } H, L;
    #pragma unroll
    for (int k = 0; k < 4; k++) {
        H.b[k] = __float2bfloat16_rn(vs[k]);
        L.b[k] = __float2bfloat16_rn(vs[k] - __bfloat162float(H.b[k]));
    }
    ((uint2*)hi)[i] = H.u;
    ((uint2*)lo)[i] = L.u;
}

// ---------------- RoPE (verified) ----------------
__global__ void rope_kernel(float* __restrict__ buf, int rowstride, int nheads)
{
    int idx = blockIdx.x * blockDim.x + threadIdx.x;
    int total = MTOT * nheads * (HDIM / 2);
    if (idx >= total) return;
    int j = idx & 63;
    int h = (idx >> 6) % nheads;
    int m = idx / (64 * nheads);
    int t = m & (SEQ - 1);
    float freq = powf(10000.0f, (float)j * (1.0f / 64.0f));
    float ang  = (float)t / freq;
    float s, c;
    sincosf(ang, &s, &c);
    float* p = buf + (size_t)m * rowstride + h * HDIM;
    float x1 = p[j], x2 = p[j + 64];
    p[j]      = x1 * c - x2 * s;
    p[j + 64] = x2 * c + x1 * s;
}

// ---------------------------------------------------------------------------
// HMMA bf16-split NT GEMM: C[m,n] = sum_k A[m,k]*B[n,k], fp32 out.
// CTA 128x128, BK=32, 8 warps (4m x 2n), warp 32x64 (m16n8k16).
// C = Ah Bh^T + Ah Bl^T + Al Bh^T.
// ---------------------------------------------------------------------------
#define GBK     32
#define G_ROWB  80                 // 32 bf16 = 64B + 16B pad
#define G_TILEB (128 * G_ROWB)     // 10240
#define G_BUFB  (4 * G_TILEB)      // Ah, Al, Bh, Bl
#define G_SMEM  (2 * G_BUFB)       // 81920

__global__ __launch_bounds__(256, 1)
void gemm_mma(const __nv_bfloat16* __restrict__ Ah, const __nv_bfloat16* __restrict__ Al,
              const __nv_bfloat16* __restrict__ Bh, const __nv_bfloat16* __restrict__ Bl,
              float* __restrict__ C, int M, int N, int K)
{
    extern __shared__ char smem[];
    const uint32_t sb0 = smem_u32(smem);
    const int tid = threadIdx.x, l = tid & 31, wid = tid >> 5;
    const int wm = wid & 3, wn = wid >> 1 & 0 ? 0 : (wid >> 2);   // wn = wid>>2
    const int mbase = blockIdx.y * 128, nbase = blockIdx.x * 128;

    // global-load mapping: 2 uint4 per matrix per thread
    const int g_row0 = tid >> 2, g_c = tid & 3;
    const int g_row1 = g_row0 + 64;

    // ldmatrix lane address offsets (bytes)
    const uint32_t laA = (uint32_t)((l & 15) * G_ROWB + (l >> 4) * 16);
    const uint32_t laB = (uint32_t)(((((l >> 4) << 3) | (l & 7)) * G_ROWB) + (((l >> 3) & 1) * 16));

    float acc[2][8][4] = {};
    uint4 rg[8];

    auto gload = [&](int kb) {
        size_t a0 = (size_t)(mbase + g_row0) * K + kb + g_c * 8;
        size_t a1 = (size_t)(mbase + g_row1) * K + kb + g_c * 8;
        size_t b0 = (size_t)(nbase + g_row0) * K + kb + g_c * 8;
        size_t b1 = (size_t)(nbase + g_row1) * K + kb + g_c * 8;
        rg[0] = *(const uint4*)(Ah + a0); rg[1] = *(const uint4*)(Ah + a1);
        rg[2] = *(const uint4*)(Al + a0); rg[3] = *(const uint4*)(Al + a1);
        rg[4] = *(const uint4*)(Bh + b0); rg[5] = *(const uint4*)(Bh + b1);
        rg[6] = *(const uint4*)(Bl + b0); rg[7] = *(const uint4*)(Bl + b1);
    };
    auto sstore = [&](int buf) {
        char* sb = smem + buf * G_BUFB;
        uint32_t o0 = (uint32_t)(g_row0 * G_ROWB + g_c * 16);
        uint32_t o1 = (uint32_t)(g_row1 * G_ROWB + g_c * 16);
        *(uint4*)(sb + 0 * G_TILEB + o0) = rg[0]; *(uint4*)(sb + 0 * G_TILEB + o1) = rg[1];
        *(uint4*)(sb + 1 * G_TILEB + o0) = rg[2]; *(uint4*)(sb + 1 * G_TILEB + o1) = rg[3];
        *(uint4*)(sb + 2 * G_TILEB + o0) = rg[4]; *(uint4*)(sb + 2 * G_TILEB + o1) = rg[5];
        *(uint4*)(sb + 3 * G_TILEB + o0) = rg[6]; *(uint4*)(sb + 3 * G_TILEB + o1) = rg[7];
    };

    gload(0);
    sstore(0);
    __syncthreads();

    const int NC = K / GBK;
    for (int i = 0; i < NC; i++) {
        if (i + 1 < NC) gload((i + 1) * GBK);

        const uint32_t base = sb0 + (uint32_t)(i & 1) * G_BUFB;
        const uint32_t sAh = base, sAl = base + G_TILEB;
        const uint32_t sBh = base + 2 * G_TILEB, sBl = base + 3 * G_TILEB;
        #pragma unroll
        for (int ks = 0; ks < 2; ks++) {
            const uint32_t koff = ks * 32;    // 16 bf16 = 32B
            uint32_t ah[2][4], al[2][4];
            #pragma unroll
            for (int mi = 0; mi < 2; mi++) {
                uint32_t ra = (uint32_t)((wm * 32 + mi * 16) * G_ROWB) + koff + laA;
                ldsm_x4(ah[mi], sAh + ra);
                ldsm_x4(al[mi], sAl + ra);
            }
            uint32_t bh[8][2], bl[8][2];
            #pragma unroll
            for (int nj2 = 0; nj2 < 4; nj2++) {
                uint32_t rb = (uint32_t)(((wn * 64) + nj2 * 16) * G_ROWB) + koff + laB;
                uint32_t t[4];
                ldsm_x4(t, sBh + rb);
                bh[2 * nj2][0] = t[0]; bh[2 * nj2][1] = t[1];
                bh[2 * nj2 + 1][0] = t[2]; bh[2 * nj2 + 1][1] = t[3];
                ldsm_x4(t, sBl + rb);
                bl[2 * nj2][0] = t[0]; bl[2 * nj2][1] = t[1];
                bl[2 * nj2 + 1][0] = t[2]; bl[2 * nj2 + 1][1] = t[3];
            }
            #pragma unroll
            for (int mi = 0; mi < 2; mi++)
                #pragma unroll
                for (int nj = 0; nj < 8; nj++) {
                    mma_bf16(acc[mi][nj], ah[mi], bh[nj]);
                    mma_bf16(acc[mi][nj], ah[mi], bl[nj]);
                    mma_bf16(acc[mi][nj], al[mi], bh[nj]);
                }
        }
        __syncthreads();
        if (i + 1 < NC) { sstore((i + 1) & 1); __syncthreads(); }
    }

    #pragma unroll
    for (int mi = 0; mi < 2; mi++) {
        int row = mbase + wm * 32 + mi * 16 + (l >> 2);
        #pragma unroll
        for (int nj = 0; nj < 8; nj++) {
            int col = nbase + wn * 64 + nj * 8 + (l & 3) * 2;
            *(float2*)&C[(size_t)row * N + col]       = make_float2(acc[mi][nj][0], acc[mi][nj][1]);
            *(float2*)&C[(size_t)(row + 8) * N + col] = make_float2(acc[mi][nj][2], acc[mi][nj][3]);
        }
    }
}

// ---------------------------------------------------------------------------
// HMMA flash attention, bf16-split, causal, GQA.
// CTA: 256 threads (8 warps), q-tile 128 rows (warp = 16 rows), kv-tile 64.
// Writes Y as bf16 hi/lo (skips the y split pass).
// ---------------------------------------------------------------------------
#define AQROWB  272                 // 128 bf16 = 256B + 16B pad
#define AQTILEB (128 * AQROWB)      // 34816
#define AKTILEB (64 * AQROWB)       // 17408
#define A_SQH   0
#define A_SQL   (A_SQH + AQTILEB)
#define A_SKH   (A_SQL + AQTILEB)
#define A_SKL   (A_SKH + AKTILEB)
#define A_SVH   (A_SKL + AKTILEB)
#define A_SVL   (A_SVH + AKTILEB)
#define A_SMEM  (A_SVL + AKTILEB)   // 139264

__global__ __launch_bounds__(256, 1)
void attn_mma(const __nv_bfloat16* __restrict__ Qh, const __nv_bfloat16* __restrict__ Ql,
              const __nv_bfloat16* __restrict__ KVh, const __nv_bfloat16* __restrict__ KVl,
              __nv_bfloat16* __restrict__ Yh, __nv_bfloat16* __restrict__ Yl)
{
    extern __shared__ char smem[];
    const uint32_t sb = smem_u32(smem);
    const int tid = threadIdx.x, l = tid & 31, wid = tid >> 5;
    const int qtile = blockIdx.x, bhidx = blockIdx.y;
    const int b = bhidx >> 4, h = bhidx & 15, kvh = h >> 2;
    const int qbase = qtile * 128;

    // load Q tile (hi/lo)
    {
        const __nv_bfloat16* qh = Qh + ((size_t)(b * SEQ + qbase)) * DMODEL + h * HDIM;
        const __nv_bfloat16* ql = Ql + ((size_t)(b * SEQ + qbase)) * DMODEL + h * HDIM;
        #pragma unroll
        for (int j = 0; j < 8; j++) {
            int s = tid + j * 256;
            int row = s >> 4, c = s & 15;
            size_t src = (size_t)row * DMODEL + c * 8;
            uint32_t dst = (uint32_t)(row * AQROWB + c * 16);
            *(uint4*)(smem + A_SQH + dst) = *(const uint4*)(qh + src);
            *(uint4*)(smem + A_SQL + dst) = *(const uint4*)(ql + src);
        }
    }

    const uint32_t laA = (uint32_t)((l & 15) * AQROWB + (l >> 4) * 16);
    const uint32_t laB = (uint32_t)(((((l >> 4) << 3) | (l & 7)) * AQROWB) + (((l >> 3) & 1) * 16));
    const uint32_t laV = (uint32_t)(((((l >> 3) & 1) * 8 + (l & 7)) * AQROWB) + ((l >> 4) * 16));

    float o[16][4] = {};
    float rm0 = -1e30f, rm1 = -1e30f, lp0 = 0.f, lp1 = 0.f;
    const float scale = 0.08838834764831845f;

    const __nv_bfloat16* kh  = KVh + (size_t)(b * SEQ) * KVDIM + kvh * HDIM;
    const __nv_bfloat16* klo = KVl + (size_t)(b * SEQ) * KVDIM + kvh * HDIM;
    const int ktiles = 2 * qtile + 2;

    for (int kt = 0; kt < ktiles; kt++) {
        const int kbase = kt * 64;
        __syncthreads();
        #pragma unroll
        for (int j = 0; j < 4; j++) {
            int s = tid + j * 256;
            int row = s >> 4, c = s & 15;
            size_t src = (size_t)(kbase + row) * KVDIM + c * 8;
            uint32_t dst = (uint32_t)(row * AQROWB + c * 16);
            *(uint4*)(smem + A_SKH + dst) = *(const uint4*)(kh + src);
            *(uint4*)(smem + A_SKL + dst) = *(const uint4*)(klo + src);
            *(uint4*)(smem + A_SVH + dst) = *(const uint4*)(kh + src + 512);
            *(uint4*)(smem + A_SVL + dst) = *(const uint4*)(klo + src + 512);
        }
        __syncthreads();

        // ---- S = Q K^T (3-product split) ----
        float s_[8][4] = {};
        #pragma unroll
        for (int ks = 0; ks < 8; ks++) {
            const uint32_t koff = ks * 32;
            uint32_t aqh[4], aql[4];
            uint32_t ra = (uint32_t)((wid * 16) * AQROWB) + koff;
            ldsm_x4(aqh, sb + A_SQH + ra + laA);
            ldsm_x4(aql, sb + A_SQL + ra + laA);
            #pragma unroll
            for (int nj2 = 0; nj2 < 4; nj2++) {
                uint32_t rb = (uint32_t)((nj2 * 16) * AQROWB) + koff + laB;
                uint32_t th[4], tl[4];
                ldsm_x4(th, sb + A_SKH + rb);
                ldsm_x4(tl, sb + A_SKL + rb);
                uint32_t bh0[2] = {th[0], th[1]}, bh1[2] = {th[2], th[3]};
                uint32_t bl0[2] = {tl[0], tl[1]}, bl1[2] = {tl[2], tl[3]};
                mma_bf16(s_[2 * nj2],     aqh, bh0);
                mma_bf16(s_[2 * nj2],     aqh, bl0);
                mma_bf16(s_[2 * nj2],     aql, bh0);
                mma_bf16(s_[2 * nj2 + 1], aqh, bh1);
                mma_bf16(s_[2 * nj2 + 1], aqh, bl1);
                mma_bf16(s_[2 * nj2 + 1], aql, bh1);
            }
        }

        // ---- scale + causal mask ----
        const int qrow0 = qbase + wid * 16 + (l >> 2);
        #pragma unroll
        for (int nj = 0; nj < 8; nj++)
            #pragma unroll
            for (int c = 0; c < 4; c++) s_[nj][c] *= scale;
        if (kbase + 63 > qbase + wid * 16) {
            #pragma unroll
            for (int nj = 0; nj < 8; nj++) {
                int kp = kbase + nj * 8 + (l & 3) * 2;
                if (kp     > qrow0)     s_[nj][0] = -1e30f;
                if (kp + 1 > qrow0)     s_[nj][1] = -1e30f;
                if (kp     > qrow0 + 8) s_[nj][2] = -1e30f;
                if (kp + 1 > qrow0 + 8) s_[nj][3] = -1e30f;
            }
        }

        // ---- online softmax (rows qrow0 and qrow0+8) ----
        float mx0 = -1e30f, mx1 = -1e30f;
        #pragma unroll
        for (int nj = 0; nj < 8; nj++) {
            mx0 = fmaxf(mx0, fmaxf(s_[nj][0], s_[nj][1]));
            mx1 = fmaxf(mx1, fmaxf(s_[nj][2], s_[nj][3]));
        }
        mx0 = fmaxf(mx0, __shfl_xor_sync(0xffffffffu, mx0, 1));
        mx0 = fmaxf(mx0, __shfl_xor_sync(0xffffffffu, mx0, 2));
        mx1 = fmaxf(mx1, __shfl_xor_sync(0xffffffffu, mx1, 1));
        mx1 = fmaxf(mx1, __shfl_xor_sync(0xffffffffu, mx1, 2));
        float nm0 = fmaxf(rm0, mx0), nm1 = fmaxf(rm1, mx1);
        float al0 = __expf(rm0 - nm0), al1 = __expf(rm1 - nm1);
        rm0 = nm0; rm1 = nm1;
        float ps0 = 0.f, ps1 = 0.f;
        #pragma unroll
        for (int nj = 0; nj < 8; nj++) {
            s_[nj][0] = __expf(s_[nj][0] - nm0);
            s_[nj][1] = __expf(s_[nj][1] - nm0);
            s_[nj][2] = __expf(s_[nj][2] - nm1);
            s_[nj][3] = __expf(s_[nj][3] - nm1);
            ps0 += s_[nj][0] + s_[nj][1];
            ps1 += s_[nj][2] + s_[nj][3];
        }
        lp0 = lp0 * al0 + ps0;
        lp1 = lp1 * al1 + ps1;
        #pragma unroll
        for (int dj = 0; dj < 16; dj++) {
            o[dj][0] *= al0; o[dj][1] *= al0;
            o[dj][2] *= al1; o[dj][3] *= al1;
        }

        // ---- O += P V (3-product split), P from s_ regs ----
        #pragma unroll
        for (int kks = 0; kks < 4; kks++) {
            uint32_t aph[4], apl[4];
            {
                const float* p0 = s_[2 * kks];
                const float* p1 = s_[2 * kks + 1];
                __nv_bfloat162 h0 = __floats2bfloat162_rn(p0[0], p0[1]);
                __nv_bfloat162 h1 = __floats2bfloat162_rn(p0[2], p0[3]);
                __nv_bfloat162 h2 = __floats2bfloat162_rn(p1[0], p1[1]);
                __nv_bfloat162 h3 = __floats2bfloat162_rn(p1[2], p1[3]);
                float2 f0 = __bfloat1622float2(h0), f1 = __bfloat1622float2(h1);
                float2 f2 = __bfloat1622float2(h2), f3 = __bfloat1622float2(h3);
                __nv_bfloat162 l0 = __floats2bfloat162_rn(p0[0] - f0.x, p0[1] - f0.y);
                __nv_bfloat162 l1 = __floats2bfloat162_rn(p0[2] - f1.x, p0[3] - f1.y);
                __nv_bfloat162 l2 = __floats2bfloat162_rn(p1[0] - f2.x, p1[1] - f2.y);
                __nv_bfloat162 l3 = __floats2bfloat162_rn(p1[2] - f3.x, p1[3] - f3.y);
                aph[0] = bf2_as_u32(h0); aph[1] = bf2_as_u32(h1);
                aph[2] = bf2_as_u32(h2); aph[3] = bf2_as_u32(h3);
                apl[0] = bf2_as_u32(l0); apl[1] = bf2_as_u32(l1);
                apl[2] = bf2_as_u32(l2); apl[3] = bf2_as_u32(l3);
            }
            uint32_t rvb = (uint32_t)((kks * 16) * AQROWB) + laV;
            #pragma unroll
            for (int dj2 = 0; dj2 < 8; dj2++) {
                uint32_t coff = dj2 * 32;
                uint32_t tvh[4], tvl[4];
                ldsm_x4_t(tvh, sb + A_SVH + rvb + coff);
                ldsm_x4_t(tvl, sb + A_SVL + rvb + coff);
                uint32_t vh0[2] = {tvh[0], tvh[1]}, vh1[2] = {tvh[2], tvh[3]};
                uint32_t vl0[2] = {tvl[0], tvl[1]}, vl1[2] = {tvl[2], tvl[3]};
                mma_bf16(o[2 * dj2],     aph, vh0);
                mma_bf16(o[2 * dj2],     aph, vl0);
                mma_bf16(o[2 * dj2],     apl, vh0);
                mma_bf16(o[2 * dj2 + 1], aph, vh1);
                mma_bf16(o[2 * dj2 + 1], aph, vl1);
                mma_bf16(o[2 * dj2 + 1], apl, vh1);
            }
        }
    }

    // ---- finalize: reduce l over quad, normalize, store bf16 hi/lo ----
    lp0 += __shfl_xor_sync(0xffffffffu, lp0, 1);
    lp0 += __shfl_xor_sync(0xffffffffu, lp0, 2);
    lp1 += __shfl_xor_sync(0xffffffffu, lp1, 1);
    lp1 += __shfl_xor_sync(0xffffffffu, lp1, 2);
    float inv0 = 1.0f / lp0, inv1 = 1.0f / lp1;

    const size_t row0 = (size_t)(b * SEQ + qbase + wid * 16 + (l >> 2));
    const int colb = h * HDIM + (l & 3) * 2;
    #pragma unroll
    for (int dj = 0; dj < 16; dj++) {
        int col = colb + dj * 8;
        float y0 = o[dj][0] * inv0, y1 = o[dj][1] * inv0;
        float y2 = o[dj][2] * inv1, y3 = o[dj][3] * inv1;
        __nv_bfloat162 hA = __floats2bfloat162_rn(y0, y1);
        float2 fA = __bfloat1622float2(hA);
        __nv_bfloat162 lA = __floats2bfloat162_rn(y0 - fA.x, y1 - fA.y);
        __nv_bfloat162 hB = __floats2bfloat162_rn(y2, y3);
        float2 fB = __bfloat1622float2(hB);
        __nv_bfloat162 lB = __floats2bfloat162_rn(y2 - fB.x, y3 - fB.y);
        *(__nv_bfloat162*)(Yh + row0 * DMODEL + col)       = hA;
        *(__nv_bfloat162*)(Yl + row0 * DMODEL + col)       = lA;
        *(__nv_bfloat162*)(Yh + (row0 + 8) * DMODEL + col) = hB;
        *(__nv_bfloat162*)(Yl + (row0 + 8) * DMODEL + col) = lB;
    }
}

// ---------------------------------------------------------------------------
extern "C" void kernel_launch(void* const* d_in, const int* in_sizes, int n_in,
                              void* d_out, int out_size)
{
    (void)in_sizes; (void)n_in; (void)out_size;
    const float* x     = (const float*)d_in[0];
    const float* Wq    = (const float*)d_in[1];
    const float* Wkv   = (const float*)d_in[2];
    const float* Wproj = (const float*)d_in[3];
    float* out = (float*)d_out;

    float *q_ptr, *kv_ptr;
    cudaGetSymbolAddress((void**)&q_ptr,  g_q);
    cudaGetSymbolAddress((void**)&kv_ptr, g_kv);
    __nv_bfloat16 *xh, *xl, *wqh, *wql, *wkh, *wkl, *wph, *wpl;
    __nv_bfloat16 *qh, *ql, *kvh, *kvl, *yh, *yl;
    cudaGetSymbolAddress((void**)&xh,  g_xh);  cudaGetSymbolAddress((void**)&xl,  g_xl);
    cudaGetSymbolAddress((void**)&wqh, g_wqh); cudaGetSymbolAddress((void**)&wql, g_wql);
    cudaGetSymbolAddress((void**)&wkh, g_wkh); cudaGetSymbolAddress((void**)&wkl, g_wkl);
    cudaGetSymbolAddress((void**)&wph, g_wph); cudaGetSymbolAddress((void**)&wpl, g_wpl);
    cudaGetSymbolAddress((void**)&qh,  g_qh);  cudaGetSymbolAddress((void**)&ql,  g_ql);
    cudaGetSymbolAddress((void**)&kvh, g_kvh); cudaGetSymbolAddress((void**)&kvl, g_kvl);
    cudaGetSymbolAddress((void**)&yh,  g_yh);  cudaGetSymbolAddress((void**)&yl,  g_yl);

    cudaFuncSetAttribute(gemm_mma, cudaFuncAttributeMaxDynamicSharedMemorySize, G_SMEM);
    cudaFuncSetAttribute(attn_mma, cudaFuncAttributeMaxDynamicSharedMemorySize, A_SMEM);

    // 0) input splits
    {
        int n;
        n = MTOT * DMODEL / 4;   split_kernel<<<n / 256, 256>>>(x,     xh,  xl,  n);
        n = DMODEL * DMODEL / 4; split_kernel<<<n / 256, 256>>>(Wq,    wqh, wql, n);
        n = KVDIM * DMODEL / 4;  split_kernel<<<n / 256, 256>>>(Wkv,   wkh, wkl, n);
        n = DMODEL * DMODEL / 4; split_kernel<<<n / 256, 256>>>(Wproj, wph, wpl, n);
    }

    // 1) Q = x Wq^T ; 2) KV = x Wkv^T
    gemm_mma<<<dim3(DMODEL / 128, MTOT / 128), 256, G_SMEM>>>(xh, xl, wqh, wql, q_ptr,
                                                              MTOT, DMODEL, DMODEL);
    gemm_mma<<<dim3(KVDIM / 128,  MTOT / 128), 256, G_SMEM>>>(xh, xl, wkh, wkl, kv_ptr,
                                                              MTOT, KVDIM, DMODEL);

    // 3) RoPE (fp32, in place)
    {
        int total_q = MTOT * NHEAD * (HDIM / 2);
        rope_kernel<<<(total_q + 255) / 256, 256>>>(q_ptr, DMODEL, NHEAD);
        int total_k = MTOT * NKV * (HDIM / 2);
        rope_kernel<<<(total_k + 255) / 256, 256>>>(kv_ptr, KVDIM, NKV);
    }

    // 4) split q, kv to bf16 hi/lo
    {
        int n = MTOT * DMODEL / 4;
        split_kernel<<<n / 256, 256>>>(q_ptr, qh, ql, n);
        n = MTOT * KVDIM / 4;
        split_kernel<<<n / 256, 256>>>(kv_ptr, kvh, kvl, n);
    }

    // 5) attention -> yh/yl (bf16 hi/lo)
    attn_mma<<<dim3(SEQ / 128, BATCH * NHEAD), 256, A_SMEM>>>(qh, ql, kvh, kvl, yh, yl);

    // 6) out = y Wproj^T
    gemm_mma<<<dim3(DMODEL / 128, MTOT / 128), 256, G_SMEM>>>(yh, yl, wph, wpl, out,
                                                              MTOT, DMODEL, DMODEL);
}

// round 4
// speedup vs baseline: 3.0417x; 1.0354x over previous
#include <cuda_runtime.h>
#include <cuda_bf16.h>
#include <cstdint>
#include <math.h>

#define BATCH  2
#define SEQ    2048
#define DMODEL 2048
#define NHEAD  16
#define NKV    4
#define HDIM   128
#define KVDIM  1024
#define MTOT   4096

// ---------------- scratch ----------------
__device__ float g_q [(size_t)MTOT * DMODEL];
__device__ float g_kv[(size_t)MTOT * KVDIM];

__device__ __nv_bfloat16 g_xh [(size_t)MTOT * DMODEL];
__device__ __nv_bfloat16 g_xl [(size_t)MTOT * DMODEL];
__device__ __nv_bfloat16 g_wqh[(size_t)DMODEL * DMODEL];
__device__ __nv_bfloat16 g_wql[(size_t)DMODEL * DMODEL];
__device__ __nv_bfloat16 g_wkh[(size_t)KVDIM * DMODEL];
__device__ __nv_bfloat16 g_wkl[(size_t)KVDIM * DMODEL];
__device__ __nv_bfloat16 g_wph[(size_t)DMODEL * DMODEL];
__device__ __nv_bfloat16 g_wpl[(size_t)DMODEL * DMODEL];
__device__ __nv_bfloat16 g_qh [(size_t)MTOT * DMODEL];
__device__ __nv_bfloat16 g_ql [(size_t)MTOT * DMODEL];
__device__ __nv_bfloat16 g_kvh[(size_t)MTOT * KVDIM];
__device__ __nv_bfloat16 g_kvl[(size_t)MTOT * KVDIM];
__device__ __nv_bfloat16 g_yh [(size_t)MTOT * DMODEL];
__device__ __nv_bfloat16 g_yl [(size_t)MTOT * DMODEL];

// ---------------- helpers ----------------
__device__ __forceinline__ uint32_t smem_u32(const void* p) {
    uint32_t a;
    asm("{ .reg .u64 t; cvta.to.shared.u64 t, %1; cvt.u32.u64 %0, t; }" : "=r"(a) : "l"(p));
    return a;
}
__device__ __forceinline__ void ldsm_x4(uint32_t* r, uint32_t addr) {
    asm volatile("ldmatrix.sync.aligned.m8n8.x4.shared.b16 {%0,%1,%2,%3}, [%4];"
                 : "=r"(r[0]), "=r"(r[1]), "=r"(r[2]), "=r"(r[3]) : "r"(addr));
}
__device__ __forceinline__ void ldsm_x4_t(uint32_t* r, uint32_t addr) {
    asm volatile("ldmatrix.sync.aligned.m8n8.x4.trans.shared.b16 {%0,%1,%2,%3}, [%4];"
                 : "=r"(r[0]), "=r"(r[1]), "=r"(r[2]), "=r"(r[3]) : "r"(addr));
}
__device__ __forceinline__ void mma_bf16(float* d, const uint32_t* a, const uint32_t* b) {
    asm volatile(
        "mma.sync.aligned.m16n8k16.row.col.f32.bf16.bf16.f32 "
        "{%0,%1,%2,%3}, {%4,%5,%6,%7}, {%8,%9}, {%0,%1,%2,%3};"
        : "+f"(d[0]), "+f"(d[1]), "+f"(d[2]), "+f"(d[3])
        : "r"(a[0]), "r"(a[1]), "r"(a[2]), "r"(a[3]), "r"(b[0]), "r"(b[1]));
}
__device__ __forceinline__ uint32_t bf2_as_u32(__nv_bfloat162 v) {
    return *reinterpret_cast<uint32_t*>(&v);
}
__device__ __forceinline__ void cp_async16(uint32_t dst, const void* src) {
    asm volatile("cp.async.cg.shared.global [%0], [%1], 16;" :: "r"(dst), "l"(src));
}
__device__ __forceinline__ void cp_commit() {
    asm volatile("cp.async.commit_group;" ::: "memory");
}
template <int N>
__device__ __forceinline__ void cp_wait() {
    asm volatile("cp.async.wait_group %0;" :: "n"(N) : "memory");
}

// ---------------- fp32 -> bf16 hi/lo split ----------------
__global__ void split_kernel(const float* __restrict__ src,
                             __nv_bfloat16* __restrict__ hi,
                             __nv_bfloat16* __restrict__ lo, int n4)
{
    int i = blockIdx.x * blockDim.x + threadIdx.x;
    if (i >= n4) return;
    float4 v = ((const float4*)src)[i];
    float vs[4] = {v.x, v.y, v.z, v.w};
    union { __nv_bfloat16 b[4]; uint2 u; } H, L;
    #pragma unroll
    for (int k = 0; k < 4; k++) {
        H.b[k] = __float2bfloat16_rn(vs[k]);
        L.b[k] = __float2bfloat16_rn(vs[k] - __bfloat162float(H.b[k]));
    }
    ((uint2*)hi)[i] = H.u;
    ((uint2*)lo)[i] = L.u;
}

// ---------------- fused RoPE + hi/lo split ----------------
__global__ void rope_split(const float* __restrict__ buf,
                           __nv_bfloat16* __restrict__ hi,
                           __nv_bfloat16* __restrict__ lo,
                           int rowstride, int nheads)
{
    int idx = blockIdx.x * blockDim.x + threadIdx.x;
    int total = MTOT * nheads * (HDIM / 2);
    if (idx >= total) return;
    int j = idx & 63;
    int h = (idx >> 6) % nheads;
    int m = idx / (64 * nheads);
    int t = m & (SEQ - 1);
    float freq = powf(10000.0f, (float)j * (1.0f / 64.0f));
    float ang  = (float)t / freq;
    float s, c;
    sincosf(ang, &s, &c);
    size_t o = (size_t)m * rowstride + h * HDIM;
    float x1 = buf[o + j], x2 = buf[o + j + 64];
    float y1 = x1 * c - x2 * s;
    float y2 = x2 * c + x1 * s;
    __nv_bfloat16 h1 = __float2bfloat16_rn(y1);
    __nv_bfloat16 h2 = __float2bfloat16_rn(y2);
    hi[o + j]      = h1;  lo[o + j]      = __float2bfloat16_rn(y1 - __bfloat162float(h1));
    hi[o + j + 64] = h2;  lo[o + j + 64] = __float2bfloat16_rn(y2 - __bfloat162float(h2));
}

// ---------------------------------------------------------------------------
// HMMA bf16-split NT GEMM, cp.async double-buffered, 2 CTAs/SM.
// CTA 128x128, BK=32, 8 warps (4m x 2n), warp 32x64.
// ---------------------------------------------------------------------------
#define GBK     32
#define G_ROWB  80
#define G_TILEB (128 * G_ROWB)     // 10240
#define G_BUFB  (4 * G_TILEB)      // 40960
#define G_SMEM  (2 * G_BUFB)       // 81920

__global__ __launch_bounds__(256, 2)
void gemm_mma(const __nv_bfloat16* __restrict__ Ah, const __nv_bfloat16* __restrict__ Al,
              const __nv_bfloat16* __restrict__ Bh, const __nv_bfloat16* __restrict__ Bl,
              float* __restrict__ C, int M, int N, int K)
{
    extern __shared__ char smem[];
    const uint32_t sb0 = smem_u32(smem);
    const int tid = threadIdx.x, l = tid & 31, wid = tid >> 5;
    const int wm = wid & 3, wn = wid >> 2;
    const int mbase = blockIdx.y * 128, nbase = blockIdx.x * 128;

    const int g_row0 = tid >> 2, g_c = tid & 3;
    const int g_row1 = g_row0 + 64;

    const uint32_t laA = (uint32_t)((l & 15) * G_ROWB + (l >> 4) * 16);
    const uint32_t laB = (uint32_t)(((((l >> 4) << 3) | (l & 7)) * G_ROWB) + (((l >> 3) & 1) * 16));

    float acc[2][8][4] = {};

    auto issue = [&](int kb, int buf) {
        const uint32_t sb = sb0 + (uint32_t)buf * G_BUFB;
        const uint32_t o0 = (uint32_t)(g_row0 * G_ROWB + g_c * 16);
        const uint32_t o1 = (uint32_t)(g_row1 * G_ROWB + g_c * 16);
        size_t a0 = (size_t)(mbase + g_row0) * K + kb + g_c * 8;
        size_t a1 = (size_t)(mbase + g_row1) * K + kb + g_c * 8;
        size_t b0 = (size_t)(nbase + g_row0) * K + kb + g_c * 8;
        size_t b1 = (size_t)(nbase + g_row1) * K + kb + g_c * 8;
        cp_async16(sb + 0 * G_TILEB + o0, Ah + a0);
        cp_async16(sb + 0 * G_TILEB + o1, Ah + a1);
        cp_async16(sb + 1 * G_TILEB + o0, Al + a0);
        cp_async16(sb + 1 * G_TILEB + o1, Al + a1);
        cp_async16(sb + 2 * G_TILEB + o0, Bh + b0);
        cp_async16(sb + 2 * G_TILEB + o1, Bh + b1);
        cp_async16(sb + 3 * G_TILEB + o0, Bl + b0);
        cp_async16(sb + 3 * G_TILEB + o1, Bl + b1);
    };

    issue(0, 0);
    cp_commit();

    const int NC = K / GBK;
    for (int i = 0; i < NC; i++) {
        cp_wait<0>();
        __syncthreads();
        if (i + 1 < NC) { issue((i + 1) * GBK, (i + 1) & 1); cp_commit(); }

        const uint32_t base = sb0 + (uint32_t)(i & 1) * G_BUFB;
        const uint32_t sAh = base, sAl = base + G_TILEB;
        const uint32_t sBh = base + 2 * G_TILEB, sBl = base + 3 * G_TILEB;
        #pragma unroll
        for (int ks = 0; ks < 2; ks++) {
            const uint32_t koff = ks * 32;
            uint32_t ah[2][4], al[2][4];
            #pragma unroll
            for (int mi = 0; mi < 2; mi++) {
                uint32_t ra = (uint32_t)((wm * 32 + mi * 16) * G_ROWB) + koff + laA;
                ldsm_x4(ah[mi], sAh + ra);
                ldsm_x4(al[mi], sAl + ra);
            }
            #pragma unroll
            for (int nj2 = 0; nj2 < 4; nj2++) {
                uint32_t rb = (uint32_t)(((wn * 64) + nj2 * 16) * G_ROWB) + koff + laB;
                uint32_t th[4], tl[4];
                ldsm_x4(th, sBh + rb);
                ldsm_x4(tl, sBl + rb);
                #pragma unroll
                for (int mi = 0; mi < 2; mi++) {
                    mma_bf16(acc[mi][2 * nj2],     ah[mi], th);
                    mma_bf16(acc[mi][2 * nj2],     ah[mi], tl);
                    mma_bf16(acc[mi][2 * nj2],     al[mi], th);
                    mma_bf16(acc[mi][2 * nj2 + 1], ah[mi], th + 2);
                    mma_bf16(acc[mi][2 * nj2 + 1], ah[mi], tl + 2);
                    mma_bf16(acc[mi][2 * nj2 + 1], al[mi], th + 2);
                }
            }
        }
    }

    #pragma unroll
    for (int mi = 0; mi < 2; mi++) {
        int row = mbase + wm * 32 + mi * 16 + (l >> 2);
        #pragma unroll
        for (int nj = 0; nj < 8; nj++) {
            int col = nbase + wn * 64 + nj * 8 + (l & 3) * 2;
            *(float2*)&C[(size_t)row * N + col]       = make_float2(acc[mi][nj][0], acc[mi][nj][1]);
            *(float2*)&C[(size_t)(row + 8) * N + col] = make_float2(acc[mi][nj][2], acc[mi][nj][3]);
        }
    }
}

// ---------------------------------------------------------------------------
// HMMA flash attention, bf16-split, causal, GQA; cp.async double-buffered KV.
// ---------------------------------------------------------------------------
#define AQROWB  272
#define AQTILEB (128 * AQROWB)      // 34816
#define AKTILEB (64 * AQROWB)       // 17408
#define A_SQH   0
#define A_SQL   (A_SQH + AQTILEB)
#define A_KV    (A_SQL + AQTILEB)   // 69632
#define A_KVSTG (4 * AKTILEB)       // 69632 per stage (Kh,Kl,Vh,Vl)
#define A_SMEM  (A_KV + 2 * A_KVSTG) // 208896

__global__ __launch_bounds__(256, 1)
void attn_mma(const __nv_bfloat16* __restrict__ Qh, const __nv_bfloat16* __restrict__ Ql,
              const __nv_bfloat16* __restrict__ KVh, const __nv_bfloat16* __restrict__ KVl,
              __nv_bfloat16* __restrict__ Yh, __nv_bfloat16* __restrict__ Yl)
{
    extern __shared__ char smem[];
    const uint32_t sb = smem_u32(smem);
    const int tid = threadIdx.x, l = tid & 31, wid = tid >> 5;
    const int qtile = blockIdx.x, bhidx = blockIdx.y;
    const int b = bhidx >> 4, h = bhidx & 15, kvh = h >> 2;
    const int qbase = qtile * 128;

    const __nv_bfloat16* kh  = KVh + (size_t)(b * SEQ) * KVDIM + kvh * HDIM;
    const __nv_bfloat16* klo = KVl + (size_t)(b * SEQ) * KVDIM + kvh * HDIM;

    // KV stage loader (cp.async): 16 chunks per thread
    auto issue_kv = [&](int kbase, int stg) {
        const uint32_t sbase = sb + A_KV + (uint32_t)stg * A_KVSTG;
        #pragma unroll
        for (int j = 0; j < 4; j++) {
            int s = tid + j * 256;
            int row = s >> 4, c = s & 15;
            size_t src = (size_t)(kbase + row) * KVDIM + c * 8;
            uint32_t dst = (uint32_t)(row * AQROWB + c * 16);
            cp_async16(sbase + 0 * AKTILEB + dst, kh  + src);
            cp_async16(sbase + 1 * AKTILEB + dst, klo + src);
            cp_async16(sbase + 2 * AKTILEB + dst, kh  + src + 512);
            cp_async16(sbase + 3 * AKTILEB + dst, klo + src + 512);
        }
    };

    // Q tile load (once)
    {
        const __nv_bfloat16* qh = Qh + ((size_t)(b * SEQ + qbase)) * DMODEL + h * HDIM;
        const __nv_bfloat16* ql = Ql + ((size_t)(b * SEQ + qbase)) * DMODEL + h * HDIM;
        #pragma unroll
        for (int j = 0; j < 8; j++) {
            int s = tid + j * 256;
            int row = s >> 4, c = s & 15;
            size_t src = (size_t)row * DMODEL + c * 8;
            uint32_t dst = (uint32_t)(row * AQROWB + c * 16);
            *(uint4*)(smem + A_SQH + dst) = *(const uint4*)(qh + src);
            *(uint4*)(smem + A_SQL + dst) = *(const uint4*)(ql + src);
        }
    }

    issue_kv(0, 0);
    cp_commit();

    const uint32_t laA = (uint32_t)((l & 15) * AQROWB + (l >> 4) * 16);
    const uint32_t laB = (uint32_t)(((((l >> 4) << 3) | (l & 7)) * AQROWB) + (((l >> 3) & 1) * 16));
    const uint32_t laV = (uint32_t)(((((l >> 3) & 1) * 8 + (l & 7)) * AQROWB) + ((l >> 4) * 16));

    float o[16][4] = {};
    float rm0 = -1e30f, rm1 = -1e30f, lp0 = 0.f, lp1 = 0.f;
    const float scale = 0.08838834764831845f;
    const int ktiles = 2 * qtile + 2;

    for (int kt = 0; kt < ktiles; kt++) {
        const int kbase = kt * 64;
        cp_wait<0>();
        __syncthreads();
        if (kt + 1 < ktiles) { issue_kv((kt + 1) * 64, (kt + 1) & 1); cp_commit(); }

        const uint32_t kvb = sb + A_KV + (uint32_t)(kt & 1) * A_KVSTG;
        const uint32_t sKH = kvb, sKL = kvb + AKTILEB;
        const uint32_t sVH = kvb + 2 * AKTILEB, sVL = kvb + 3 * AKTILEB;

        // ---- S = Q K^T ----
        float s_[8][4] = {};
        #pragma unroll
        for (int ks = 0; ks < 8; ks++) {
            const uint32_t koff = ks * 32;
            uint32_t aqh[4], aql[4];
            uint32_t ra = (uint32_t)((wid * 16) * AQROWB) + koff;
            ldsm_x4(aqh, sb + A_SQH + ra + laA);
            ldsm_x4(aql, sb + A_SQL + ra + laA);
            #pragma unroll
            for (int nj2 = 0; nj2 < 4; nj2++) {
                uint32_t rb = (uint32_t)((nj2 * 16) * AQROWB) + koff + laB;
                uint32_t th[4], tl[4];
                ldsm_x4(th, sKH + rb);
                ldsm_x4(tl, sKL + rb);
                mma_bf16(s_[2 * nj2],     aqh, th);
                mma_bf16(s_[2 * nj2],     aqh, tl);
                mma_bf16(s_[2 * nj2],     aql, th);
                mma_bf16(s_[2 * nj2 + 1], aqh, th + 2);
                mma_bf16(s_[2 * nj2 + 1], aqh, tl + 2);
                mma_bf16(s_[2 * nj2 + 1], aql, th + 2);
            }
        }

        // ---- scale + causal mask ----
        const int qrow0 = qbase + wid * 16 + (l >> 2);
        #pragma unroll
        for (int nj = 0; nj < 8; nj++)
            #pragma unroll
            for (int c = 0; c < 4; c++) s_[nj][c] *= scale;
        if (kbase + 63 > qbase + wid * 16) {
            #pragma unroll
            for (int nj = 0; nj < 8; nj++) {
                int kp = kbase + nj * 8 + (l & 3) * 2;
                if (kp     > qrow0)     s_[nj][0] = -1e30f;
                if (kp + 1 > qrow0)     s_[nj][1] = -1e30f;
                if (kp     > qrow0 + 8) s_[nj][2] = -1e30f;
                if (kp + 1 > qrow0 + 8) s_[nj][3] = -1e30f;
            }
        }

        // ---- online softmax ----
        float mx0 = -1e30f, mx1 = -1e30f;
        #pragma unroll
        for (int nj = 0; nj < 8; nj++) {
            mx0 = fmaxf(mx0, fmaxf(s_[nj][0], s_[nj][1]));
            mx1 = fmaxf(mx1, fmaxf(s_[nj][2], s_[nj][3]));
        }
        mx0 = fmaxf(mx0, __shfl_xor_sync(0xffffffffu, mx0, 1));
        mx0 = fmaxf(mx0, __shfl_xor_sync(0xffffffffu, mx0, 2));
        mx1 = fmaxf(mx1, __shfl_xor_sync(0xffffffffu, mx1, 1));
        mx1 = fmaxf(mx1, __shfl_xor_sync(0xffffffffu, mx1, 2));
        float nm0 = fmaxf(rm0, mx0), nm1 = fmaxf(rm1, mx1);
        float al0 = __expf(rm0 - nm0), al1 = __expf(rm1 - nm1);
        rm0 = nm0; rm1 = nm1;
        float ps0 = 0.f, ps1 = 0.f;
        #pragma unroll
        for (int nj = 0; nj < 8; nj++) {
            s_[nj][0] = __expf(s_[nj][0] - nm0);
            s_[nj][1] = __expf(s_[nj][1] - nm0);
            s_[nj][2] = __expf(s_[nj][2] - nm1);
            s_[nj][3] = __expf(s_[nj][3] - nm1);
            ps0 += s_[nj][0] + s_[nj][1];
            ps1 += s_[nj][2] + s_[nj][3];
        }
        lp0 = lp0 * al0 + ps0;
        lp1 = lp1 * al1 + ps1;
        #pragma unroll
        for (int dj = 0; dj < 16; dj++) {
            o[dj][0] *= al0; o[dj][1] *= al0;
            o[dj][2] *= al1; o[dj][3] *= al1;
        }

        // ---- O += P V ----
        #pragma unroll
        for (int kks = 0; kks < 4; kks++) {
            uint32_t aph[4], apl[4];
            {
                const float* p0 = s_[2 * kks];
                const float* p1 = s_[2 * kks + 1];
                __nv_bfloat162 h0 = __floats2bfloat162_rn(p0[0], p0[1]);
                __nv_bfloat162 h1 = __floats2bfloat162_rn(p0[2], p0[3]);
                __nv_bfloat162 h2 = __floats2bfloat162_rn(p1[0], p1[1]);
                __nv_bfloat162 h3 = __floats2bfloat162_rn(p1[2], p1[3]);
                float2 f0 = __bfloat1622float2(h0), f1 = __bfloat1622float2(h1);
                float2 f2 = __bfloat1622float2(h2), f3 = __bfloat1622float2(h3);
                __nv_bfloat162 l0 = __floats2bfloat162_rn(p0[0] - f0.x, p0[1] - f0.y);
                __nv_bfloat162 l1 = __floats2bfloat162_rn(p0[2] - f1.x, p0[3] - f1.y);
                __nv_bfloat162 l2 = __floats2bfloat162_rn(p1[0] - f2.x, p1[1] - f2.y);
                __nv_bfloat162 l3 = __floats2bfloat162_rn(p1[2] - f3.x, p1[3] - f3.y);
                aph[0] = bf2_as_u32(h0); aph[1] = bf2_as_u32(h1);
                aph[2] = bf2_as_u32(h2); aph[3] = bf2_as_u32(h3);
                apl[0] = bf2_as_u32(l0); apl[1] = bf2_as_u32(l1);
                apl[2] = bf2_as_u32(l2); apl[3] = bf2_as_u32(l3);
            }
            uint32_t rvb = (uint32_t)((kks * 16) * AQROWB) + laV;
            #pragma unroll
            for (int dj2 = 0; dj2 < 8; dj2++) {
                uint32_t coff = dj2 * 32;
                uint32_t tvh[4], tvl[4];
                ldsm_x4_t(tvh, sVH + rvb + coff);
                ldsm_x4_t(tvl, sVL + rvb + coff);
                mma_bf16(o[2 * dj2],     aph, tvh);
                mma_bf16(o[2 * dj2],     aph, tvl);
                mma_bf16(o[2 * dj2],     apl, tvh);
                mma_bf16(o[2 * dj2 + 1], aph, tvh + 2);
                mma_bf16(o[2 * dj2 + 1], aph, tvl + 2);
                mma_bf16(o[2 * dj2 + 1], apl, tvh + 2);
            }
        }
    }

    // ---- finalize ----
    lp0 += __shfl_xor_sync(0xffffffffu, lp0, 1);
    lp0 += __shfl_xor_sync(0xffffffffu, lp0, 2);
    lp1 += __shfl_xor_sync(0xffffffffu, lp1, 1);
    lp1 += __shfl_xor_sync(0xffffffffu, lp1, 2);
    float inv0 = 1.0f / lp0, inv1 = 1.0f / lp1;

    const size_t row0 = (size_t)(b * SEQ + qbase + wid * 16 + (l >> 2));
    const int colb = h * HDIM + (l & 3) * 2;
    #pragma unroll
    for (int dj = 0; dj < 16; dj++) {
        int col = colb + dj * 8;
        float y0 = o[dj][0] * inv0, y1 = o[dj][1] * inv0;
        float y2 = o[dj][2] * inv1, y3 = o[dj][3] * inv1;
        __nv_bfloat162 hA = __floats2bfloat162_rn(y0, y1);
        float2 fA = __bfloat1622float2(hA);
        __nv_bfloat162 lA = __floats2bfloat162_rn(y0 - fA.x, y1 - fA.y);
        __nv_bfloat162 hB = __floats2bfloat162_rn(y2, y3);
        float2 fB = __bfloat1622float2(hB);
        __nv_bfloat162 lB = __floats2bfloat162_rn(y2 - fB.x, y3 - fB.y);
        *(__nv_bfloat162*)(Yh + row0 * DMODEL + col)       = hA;
        *(__nv_bfloat162*)(Yl + row0 * DMODEL + col)       = lA;
        *(__nv_bfloat162*)(Yh + (row0 + 8) * DMODEL + col) = hB;
        *(__nv_bfloat162*)(Yl + (row0 + 8) * DMODEL + col) = lB;
    }
}

// ---------------------------------------------------------------------------
extern "C" void kernel_launch(void* const* d_in, const int* in_sizes, int n_in,
                              void* d_out, int out_size)
{
    (void)in_sizes; (void)n_in; (void)out_size;
    const float* x     = (const float*)d_in[0];
    const float* Wq    = (const float*)d_in[1];
    const float* Wkv   = (const float*)d_in[2];
    const float* Wproj = (const float*)d_in[3];
    float* out = (float*)d_out;

    float *q_ptr, *kv_ptr;
    cudaGetSymbolAddress((void**)&q_ptr,  g_q);
    cudaGetSymbolAddress((void**)&kv_ptr, g_kv);
    __nv_bfloat16 *xh, *xl, *wqh, *wql, *wkh, *wkl, *wph, *wpl;
    __nv_bfloat16 *qh, *ql, *kvh, *kvl, *yh, *yl;
    cudaGetSymbolAddress((void**)&xh,  g_xh);  cudaGetSymbolAddress((void**)&xl,  g_xl);
    cudaGetSymbolAddress((void**)&wqh, g_wqh); cudaGetSymbolAddress((void**)&wql, g_wql);
    cudaGetSymbolAddress((void**)&wkh, g_wkh); cudaGetSymbolAddress((void**)&wkl, g_wkl);
    cudaGetSymbolAddress((void**)&wph, g_wph); cudaGetSymbolAddress((void**)&wpl, g_wpl);
    cudaGetSymbolAddress((void**)&qh,  g_qh);  cudaGetSymbolAddress((void**)&ql,  g_ql);
    cudaGetSymbolAddress((void**)&kvh, g_kvh); cudaGetSymbolAddress((void**)&kvl, g_kvl);
    cudaGetSymbolAddress((void**)&yh,  g_yh);  cudaGetSymbolAddress((void**)&yl,  g_yl);

    cudaFuncSetAttribute(gemm_mma, cudaFuncAttributeMaxDynamicSharedMemorySize, G_SMEM);
    cudaFuncSetAttribute(attn_mma, cudaFuncAttributeMaxDynamicSharedMemorySize, A_SMEM);

    // 0) input splits
    {
        int n;
        n = MTOT * DMODEL / 4;   split_kernel<<<n / 256, 256>>>(x,     xh,  xl,  n);
        n = DMODEL * DMODEL / 4; split_kernel<<<n / 256, 256>>>(Wq,    wqh, wql, n);
        n = KVDIM * DMODEL / 4;  split_kernel<<<n / 256, 256>>>(Wkv,   wkh, wkl, n);
        n = DMODEL * DMODEL / 4; split_kernel<<<n / 256, 256>>>(Wproj, wph, wpl, n);
    }

    // 1) Q = x Wq^T ; 2) KV = x Wkv^T
    gemm_mma<<<dim3(DMODEL / 128, MTOT / 128), 256, G_SMEM>>>(xh, xl, wqh, wql, q_ptr,
                                                              MTOT, DMODEL, DMODEL);
    gemm_mma<<<dim3(KVDIM / 128,  MTOT / 128), 256, G_SMEM>>>(xh, xl, wkh, wkl, kv_ptr,
                                                              MTOT, KVDIM, DMODEL);

    // 3) fused rope+split for q; plain split then rope-overwrite for kv
    {
        int total_q = MTOT * NHEAD * (HDIM / 2);
        rope_split<<<(total_q + 255) / 256, 256>>>(q_ptr, qh, ql, DMODEL, NHEAD);
        int n = MTOT * KVDIM / 4;
        split_kernel<<<n / 256, 256>>>(kv_ptr, kvh, kvl, n);
        int total_k = MTOT * NKV * (HDIM / 2);
        rope_split<<<(total_k + 255) / 256, 256>>>(kv_ptr, kvh, kvl, KVDIM, NKV);
    }

    // 4) attention -> yh/yl
    attn_mma<<<dim3(SEQ / 128, BATCH * NHEAD), 256, A_SMEM>>>(qh, ql, kvh, kvl, yh, yl);

    // 5) out = y Wproj^T
    gemm_mma<<<dim3(DMODEL / 128, MTOT / 128), 256, G_SMEM>>>(yh, yl, wph, wpl, out,
                                                              MTOT, DMODEL, DMODEL);
}

// round 5
// speedup vs baseline: 4.4227x; 1.4540x over previous
#include <cuda_runtime.h>
#include <cuda_fp16.h>
#include <cstdint>
#include <math.h>

#define BATCH  2
#define SEQ    2048
#define DMODEL 2048
#define NHEAD  16
#define NKV    4
#define HDIM   128
#define KVDIM  1024
#define MTOT   4096

// ---------------- scratch ----------------
__device__ float g_q [(size_t)MTOT * DMODEL];
__device__ float g_kv[(size_t)MTOT * KVDIM];

__device__ __half g_xh [(size_t)MTOT * DMODEL];
__device__ __half g_xl [(size_t)MTOT * DMODEL];
__device__ __half g_wqh[(size_t)DMODEL * DMODEL];
__device__ __half g_wkh[(size_t)KVDIM * DMODEL];
__device__ __half g_wph[(size_t)DMODEL * DMODEL];
__device__ __half g_qh [(size_t)MTOT * DMODEL];
__device__ __half g_ql [(size_t)MTOT * DMODEL];
__device__ __half g_kvh[(size_t)MTOT * KVDIM];
__device__ __half g_yh [(size_t)MTOT * DMODEL];
__device__ __half g_yl [(size_t)MTOT * DMODEL];

// ---------------- helpers ----------------
__device__ __forceinline__ uint32_t smem_u32(const void* p) {
    uint32_t a;
    asm("{ .reg .u64 t; cvta.to.shared.u64 t, %1; cvt.u32.u64 %0, t; }" : "=r"(a) : "l"(p));
    return a;
}
__device__ __forceinline__ void ldsm_x4(uint32_t* r, uint32_t addr) {
    asm volatile("ldmatrix.sync.aligned.m8n8.x4.shared.b16 {%0,%1,%2,%3}, [%4];"
                 : "=r"(r[0]), "=r"(r[1]), "=r"(r[2]), "=r"(r[3]) : "r"(addr));
}
__device__ __forceinline__ void ldsm_x4_t(uint32_t* r, uint32_t addr) {
    asm volatile("ldmatrix.sync.aligned.m8n8.x4.trans.shared.b16 {%0,%1,%2,%3}, [%4];"
                 : "=r"(r[0]), "=r"(r[1]), "=r"(r[2]), "=r"(r[3]) : "r"(addr));
}
__device__ __forceinline__ void mma_f16(float* d, const uint32_t* a, const uint32_t* b) {
    asm volatile(
        "mma.sync.aligned.m16n8k16.row.col.f32.f16.f16.f32 "
        "{%0,%1,%2,%3}, {%4,%5,%6,%7}, {%8,%9}, {%0,%1,%2,%3};"
        : "+f"(d[0]), "+f"(d[1]), "+f"(d[2]), "+f"(d[3])
        : "r"(a[0]), "r"(a[1]), "r"(a[2]), "r"(a[3]), "r"(b[0]), "r"(b[1]));
}
__device__ __forceinline__ uint32_t h2_as_u32(__half2 v) {
    return *reinterpret_cast<uint32_t*>(&v);
}
__device__ __forceinline__ void cp_async16(uint32_t dst, const void* src) {
    asm volatile("cp.async.cg.shared.global [%0], [%1], 16;" :: "r"(dst), "l"(src));
}
__device__ __forceinline__ void cp_commit() {
    asm volatile("cp.async.commit_group;" ::: "memory");
}
template <int N>
__device__ __forceinline__ void cp_wait() {
    asm volatile("cp.async.wait_group %0;" :: "n"(N) : "memory");
}

// ---------------- fp32 -> fp16 hi/lo split ----------------
__global__ void split_kernel(const float* __restrict__ src,
                             __half* __restrict__ hi,
                             __half* __restrict__ lo, int n4)
{
    int i = blockIdx.x * blockDim.x + threadIdx.x;
    if (i >= n4) return;
    float4 v = ((const float4*)src)[i];
    float vs[4] = {v.x, v.y, v.z, v.w};
    union { __half b[4]; uint2 u; } H, L;
    #pragma unroll
    for (int k = 0; k < 4; k++) {
        H.b[k] = __float2half_rn(vs[k]);
        L.b[k] = __float2half_rn(vs[k] - __half2float(H.b[k]));
    }
    ((uint2*)hi)[i] = H.u;
    ((uint2*)lo)[i] = L.u;
}

// ---------------- fp32 -> fp16 (hi only) ----------------
__global__ void cvt_kernel(const float* __restrict__ src,
                           __half* __restrict__ dst, int n4)
{
    int i = blockIdx.x * blockDim.x + threadIdx.x;
    if (i >= n4) return;
    float4 v = ((const float4*)src)[i];
    union { __half b[4]; uint2 u; } H;
    H.b[0] = __float2half_rn(v.x); H.b[1] = __float2half_rn(v.y);
    H.b[2] = __float2half_rn(v.z); H.b[3] = __float2half_rn(v.w);
    ((uint2*)dst)[i] = H.u;
}

// ---------------- fused RoPE + fp16 hi/lo split (for q) ----------------
__global__ void rope_split(const float* __restrict__ buf,
                           __half* __restrict__ hi,
                           __half* __restrict__ lo,
                           int rowstride, int nheads)
{
    int idx = blockIdx.x * blockDim.x + threadIdx.x;
    int total = MTOT * nheads * (HDIM / 2);
    if (idx >= total) return;
    int j = idx & 63;
    int h = (idx >> 6) % nheads;
    int m = idx / (64 * nheads);
    int t = m & (SEQ - 1);
    float freq = powf(10000.0f, (float)j * (1.0f / 64.0f));
    float ang  = (float)t / freq;
    float s, c;
    sincosf(ang, &s, &c);
    size_t o = (size_t)m * rowstride + h * HDIM;
    float x1 = buf[o + j], x2 = buf[o + j + 64];
    float y1 = x1 * c - x2 * s;
    float y2 = x2 * c + x1 * s;
    __half h1 = __float2half_rn(y1);
    __half h2 = __float2half_rn(y2);
    hi[o + j]      = h1;  lo[o + j]      = __float2half_rn(y1 - __half2float(h1));
    hi[o + j + 64] = h2;  lo[o + j + 64] = __float2half_rn(y2 - __half2float(h2));
}

// ---------------- RoPE -> fp16 hi only (for k half of kv) ----------------
__global__ void rope_cvt(const float* __restrict__ buf,
                         __half* __restrict__ hi,
                         int rowstride, int nheads)
{
    int idx = blockIdx.x * blockDim.x + threadIdx.x;
    int total = MTOT * nheads * (HDIM / 2);
    if (idx >= total) return;
    int j = idx & 63;
    int h = (idx >> 6) % nheads;
    int m = idx / (64 * nheads);
    int t = m & (SEQ - 1);
    float freq = powf(10000.0f, (float)j * (1.0f / 64.0f));
    float ang  = (float)t / freq;
    float s, c;
    sincosf(ang, &s, &c);
    size_t o = (size_t)m * rowstride + h * HDIM;
    float x1 = buf[o + j], x2 = buf[o + j + 64];
    hi[o + j]      = __float2half_rn(x1 * c - x2 * s);
    hi[o + j + 64] = __float2half_rn(x2 * c + x1 * s);
}

// ---------------------------------------------------------------------------
// HMMA fp16 2-product NT GEMM: C = (Ah+Al) Bh^T, fp32 accum/out.
// CTA 128x128, BK=32, 8 warps (4m x 2n), cp.async double-buffered, 2 CTA/SM.
// ---------------------------------------------------------------------------
#define GBK     32
#define G_ROWB  80
#define G_TILEB (128 * G_ROWB)     // 10240
#define G_STGB  (3 * G_TILEB)      // 30720 (Ah, Al, Bh)
#define G_SMEM  (2 * G_STGB)       // 61440

__global__ __launch_bounds__(256, 2)
void gemm_mma(const __half* __restrict__ Ah, const __half* __restrict__ Al,
              const __half* __restrict__ Bh,
              float* __restrict__ C, int M, int N, int K)
{
    extern __shared__ char smem[];
    const uint32_t sb0 = smem_u32(smem);
    const int tid = threadIdx.x, l = tid & 31, wid = tid >> 5;
    const int wm = wid & 3, wn = wid >> 2;
    const int mbase = blockIdx.y * 128, nbase = blockIdx.x * 128;

    const int g_row0 = tid >> 2, g_c = tid & 3;
    const int g_row1 = g_row0 + 64;

    const uint32_t laA = (uint32_t)((l & 15) * G_ROWB + (l >> 4) * 16);
    const uint32_t laB = (uint32_t)(((((l >> 4) << 3) | (l & 7)) * G_ROWB) + (((l >> 3) & 1) * 16));

    float acc[2][8][4] = {};

    auto issue = [&](int kb, int buf) {
        const uint32_t sb = sb0 + (uint32_t)buf * G_STGB;
        const uint32_t o0 = (uint32_t)(g_row0 * G_ROWB + g_c * 16);
        const uint32_t o1 = (uint32_t)(g_row1 * G_ROWB + g_c * 16);
        size_t a0 = (size_t)(mbase + g_row0) * K + kb + g_c * 8;
        size_t a1 = (size_t)(mbase + g_row1) * K + kb + g_c * 8;
        size_t b0 = (size_t)(nbase + g_row0) * K + kb + g_c * 8;
        size_t b1 = (size_t)(nbase + g_row1) * K + kb + g_c * 8;
        cp_async16(sb + 0 * G_TILEB + o0, Ah + a0);
        cp_async16(sb + 0 * G_TILEB + o1, Ah + a1);
        cp_async16(sb + 1 * G_TILEB + o0, Al + a0);
        cp_async16(sb + 1 * G_TILEB + o1, Al + a1);
        cp_async16(sb + 2 * G_TILEB + o0, Bh + b0);
        cp_async16(sb + 2 * G_TILEB + o1, Bh + b1);
    };

    issue(0, 0);
    cp_commit();

    const int NC = K / GBK;
    for (int i = 0; i < NC; i++) {
        cp_wait<0>();
        __syncthreads();
        if (i + 1 < NC) { issue((i + 1) * GBK, (i + 1) & 1); cp_commit(); }

        const uint32_t base = sb0 + (uint32_t)(i & 1) * G_STGB;
        const uint32_t sAh = base, sAl = base + G_TILEB, sBh = base + 2 * G_TILEB;
        #pragma unroll
        for (int ks = 0; ks < 2; ks++) {
            const uint32_t koff = ks * 32;
            uint32_t ah[2][4], al[2][4];
            #pragma unroll
            for (int mi = 0; mi < 2; mi++) {
                uint32_t ra = (uint32_t)((wm * 32 + mi * 16) * G_ROWB) + koff + laA;
                ldsm_x4(ah[mi], sAh + ra);
                ldsm_x4(al[mi], sAl + ra);
            }
            #pragma unroll
            for (int nj2 = 0; nj2 < 4; nj2++) {
                uint32_t rb = (uint32_t)(((wn * 64) + nj2 * 16) * G_ROWB) + koff + laB;
                uint32_t th[4];
                ldsm_x4(th, sBh + rb);
                #pragma unroll
                for (int mi = 0; mi < 2; mi++) {
                    mma_f16(acc[mi][2 * nj2],     ah[mi], th);
                    mma_f16(acc[mi][2 * nj2],     al[mi], th);
                    mma_f16(acc[mi][2 * nj2 + 1], ah[mi], th + 2);
                    mma_f16(acc[mi][2 * nj2 + 1], al[mi], th + 2);
                }
            }
        }
    }

    #pragma unroll
    for (int mi = 0; mi < 2; mi++) {
        int row = mbase + wm * 32 + mi * 16 + (l >> 2);
        #pragma unroll
        for (int nj = 0; nj < 8; nj++) {
            int col = nbase + wn * 64 + nj * 8 + (l & 3) * 2;
            *(float2*)&C[(size_t)row * N + col]       = make_float2(acc[mi][nj][0], acc[mi][nj][1]);
            *(float2*)&C[(size_t)(row + 8) * N + col] = make_float2(acc[mi][nj][2], acc[mi][nj][3]);
        }
    }
}

// ---------------------------------------------------------------------------
// HMMA fp16 flash attention, causal, GQA; cp.async double-buffered KV.
// S = (Qh+Ql) Kh^T;  O += (Ph+Pl) Vh.  K/V single fp16.
// ---------------------------------------------------------------------------
#define AQROWB  272
#define AQTILEB (128 * AQROWB)      // 34816
#define AKTILEB (64 * AQROWB)       // 17408
#define A_SQH   0
#define A_SQL   (A_SQH + AQTILEB)
#define A_KV    (A_SQL + AQTILEB)    // 69632
#define A_KVSTG (2 * AKTILEB)        // 34816 (Kh, Vh)
#define A_SMEM  (A_KV + 2 * A_KVSTG) // 139264

__global__ __launch_bounds__(256, 1)
void attn_mma(const __half* __restrict__ Qh, const __half* __restrict__ Ql,
              const __half* __restrict__ KVh,
              __half* __restrict__ Yh, __half* __restrict__ Yl)
{
    extern __shared__ char smem[];
    const uint32_t sb = smem_u32(smem);
    const int tid = threadIdx.x, l = tid & 31, wid = tid >> 5;
    const int qtile = blockIdx.x, bhidx = blockIdx.y;
    const int b = bhidx >> 4, h = bhidx & 15, kvh = h >> 2;
    const int qbase = qtile * 128;

    const __half* kp = KVh + (size_t)(b * SEQ) * KVDIM + kvh * HDIM;

    auto issue_kv = [&](int kbase, int stg) {
        const uint32_t sbase = sb + A_KV + (uint32_t)stg * A_KVSTG;
        #pragma unroll
        for (int j = 0; j < 4; j++) {
            int s = tid + j * 256;
            int row = s >> 4, c = s & 15;
            size_t src = (size_t)(kbase + row) * KVDIM + c * 8;
            uint32_t dst = (uint32_t)(row * AQROWB + c * 16);
            cp_async16(sbase + 0 * AKTILEB + dst, kp + src);          // K
            cp_async16(sbase + 1 * AKTILEB + dst, kp + src + 512);    // V
        }
    };

    // Q tile load (once)
    {
        const __half* qh = Qh + ((size_t)(b * SEQ + qbase)) * DMODEL + h * HDIM;
        const __half* ql = Ql + ((size_t)(b * SEQ + qbase)) * DMODEL + h * HDIM;
        #pragma unroll
        for (int j = 0; j < 8; j++) {
            int s = tid + j * 256;
            int row = s >> 4, c = s & 15;
            size_t src = (size_t)row * DMODEL + c * 8;
            uint32_t dst = (uint32_t)(row * AQROWB + c * 16);
            *(uint4*)(smem + A_SQH + dst) = *(const uint4*)(qh + src);
            *(uint4*)(smem + A_SQL + dst) = *(const uint4*)(ql + src);
        }
    }

    issue_kv(0, 0);
    cp_commit();

    const uint32_t laA = (uint32_t)((l & 15) * AQROWB + (l >> 4) * 16);
    const uint32_t laB = (uint32_t)(((((l >> 4) << 3) | (l & 7)) * AQROWB) + (((l >> 3) & 1) * 16));
    const uint32_t laV = (uint32_t)(((((l >> 3) & 1) * 8 + (l & 7)) * AQROWB) + ((l >> 4) * 16));

    float o[16][4] = {};
    float rm0 = -1e30f, rm1 = -1e30f, lp0 = 0.f, lp1 = 0.f;
    const float scale = 0.08838834764831845f;
    const int ktiles = 2 * qtile + 2;

    for (int kt = 0; kt < ktiles; kt++) {
        const int kbase = kt * 64;
        cp_wait<0>();
        __syncthreads();
        if (kt + 1 < ktiles) { issue_kv((kt + 1) * 64, (kt + 1) & 1); cp_commit(); }

        const uint32_t kvb = sb + A_KV + (uint32_t)(kt & 1) * A_KVSTG;
        const uint32_t sKH = kvb, sVH = kvb + AKTILEB;

        // ---- S = Q K^T ----
        float s_[8][4] = {};
        #pragma unroll
        for (int ks = 0; ks < 8; ks++) {
            const uint32_t koff = ks * 32;
            uint32_t aqh[4], aql[4];
            uint32_t ra = (uint32_t)((wid * 16) * AQROWB) + koff;
            ldsm_x4(aqh, sb + A_SQH + ra + laA);
            ldsm_x4(aql, sb + A_SQL + ra + laA);
            #pragma unroll
            for (int nj2 = 0; nj2 < 4; nj2++) {
                uint32_t rb = (uint32_t)((nj2 * 16) * AQROWB) + koff + laB;
                uint32_t th[4];
                ldsm_x4(th, sKH + rb);
                mma_f16(s_[2 * nj2],     aqh, th);
                mma_f16(s_[2 * nj2],     aql, th);
                mma_f16(s_[2 * nj2 + 1], aqh, th + 2);
                mma_f16(s_[2 * nj2 + 1], aql, th + 2);
            }
        }

        // ---- scale + causal mask ----
        const int qrow0 = qbase + wid * 16 + (l >> 2);
        #pragma unroll
        for (int nj = 0; nj < 8; nj++)
            #pragma unroll
            for (int c = 0; c < 4; c++) s_[nj][c] *= scale;
        if (kbase + 63 > qbase + wid * 16) {
            #pragma unroll
            for (int nj = 0; nj < 8; nj++) {
                int kp2 = kbase + nj * 8 + (l & 3) * 2;
                if (kp2     > qrow0)     s_[nj][0] = -1e30f;
                if (kp2 + 1 > qrow0)     s_[nj][1] = -1e30f;
                if (kp2     > qrow0 + 8) s_[nj][2] = -1e30f;
                if (kp2 + 1 > qrow0 + 8) s_[nj][3] = -1e30f;
            }
        }

        // ---- online softmax ----
        float mx0 = -1e30f, mx1 = -1e30f;
        #pragma unroll
        for (int nj = 0; nj < 8; nj++) {
            mx0 = fmaxf(mx0, fmaxf(s_[nj][0], s_[nj][1]));
            mx1 = fmaxf(mx1, fmaxf(s_[nj][2], s_[nj][3]));
        }
        mx0 = fmaxf(mx0, __shfl_xor_sync(0xffffffffu, mx0, 1));
        mx0 = fmaxf(mx0, __shfl_xor_sync(0xffffffffu, mx0, 2));
        mx1 = fmaxf(mx1, __shfl_xor_sync(0xffffffffu, mx1, 1));
        mx1 = fmaxf(mx1, __shfl_xor_sync(0xffffffffu, mx1, 2));
        float nm0 = fmaxf(rm0, mx0), nm1 = fmaxf(rm1, mx1);
        float al0 = __expf(rm0 - nm0), al1 = __expf(rm1 - nm1);
        rm0 = nm0; rm1 = nm1;
        float ps0 = 0.f, ps1 = 0.f;
        #pragma unroll
        for (int nj = 0; nj < 8; nj++) {
            s_[nj][0] = __expf(s_[nj][0] - nm0);
            s_[nj][1] = __expf(s_[nj][1] - nm0);
            s_[nj][2] = __expf(s_[nj][2] - nm1);
            s_[nj][3] = __expf(s_[nj][3] - nm1);
            ps0 += s_[nj][0] + s_[nj][1];
            ps1 += s_[nj][2] + s_[nj][3];
        }
        lp0 = lp0 * al0 + ps0;
        lp1 = lp1 * al1 + ps1;
        #pragma unroll
        for (int dj = 0; dj < 16; dj++) {
            o[dj][0] *= al0; o[dj][1] *= al0;
            o[dj][2] *= al1; o[dj][3] *= al1;
        }

        // ---- O += P V ----
        #pragma unroll
        for (int kks = 0; kks < 4; kks++) {
            uint32_t aph[4], apl[4];
            {
                const float* p0 = s_[2 * kks];
                const float* p1 = s_[2 * kks + 1];
                __half2 h0 = __floats2half2_rn(p0[0], p0[1]);
                __half2 h1 = __floats2half2_rn(p0[2], p0[3]);
                __half2 h2 = __floats2half2_rn(p1[0], p1[1]);
                __half2 h3 = __floats2half2_rn(p1[2], p1[3]);
                float2 f0 = __half22float2(h0), f1 = __half22float2(h1);
                float2 f2 = __half22float2(h2), f3 = __half22float2(h3);
                __half2 l0 = __floats2half2_rn(p0[0] - f0.x, p0[1] - f0.y);
                __half2 l1 = __floats2half2_rn(p0[2] - f1.x, p0[3] - f1.y);
                __half2 l2 = __floats2half2_rn(p1[0] - f2.x, p1[1] - f2.y);
                __half2 l3 = __floats2half2_rn(p1[2] - f3.x, p1[3] - f3.y);
                aph[0] = h2_as_u32(h0); aph[1] = h2_as_u32(h1);
                aph[2] = h2_as_u32(h2); aph[3] = h2_as_u32(h3);
                apl[0] = h2_as_u32(l0); apl[1] = h2_as_u32(l1);
                apl[2] = h2_as_u32(l2); apl[3] = h2_as_u32(l3);
            }
            uint32_t rvb = (uint32_t)((kks * 16) * AQROWB) + laV;
            #pragma unroll
            for (int dj2 = 0; dj2 < 8; dj2++) {
                uint32_t coff = dj2 * 32;
                uint32_t tvh[4];
                ldsm_x4_t(tvh, sVH + rvb + coff);
                mma_f16(o[2 * dj2],     aph, tvh);
                mma_f16(o[2 * dj2],     apl, tvh);
                mma_f16(o[2 * dj2 + 1], aph, tvh + 2);
                mma_f16(o[2 * dj2 + 1], apl, tvh + 2);
            }
        }
    }

    // ---- finalize ----
    lp0 += __shfl_xor_sync(0xffffffffu, lp0, 1);
    lp0 += __shfl_xor_sync(0xffffffffu, lp0, 2);
    lp1 += __shfl_xor_sync(0xffffffffu, lp1, 1);
    lp1 += __shfl_xor_sync(0xffffffffu, lp1, 2);
    float inv0 = 1.0f / lp0, inv1 = 1.0f / lp1;

    const size_t row0 = (size_t)(b * SEQ + qbase + wid * 16 + (l >> 2));
    const int colb = h * HDIM + (l & 3) * 2;
    #pragma unroll
    for (int dj = 0; dj < 16; dj++) {
        int col = colb + dj * 8;
        float y0 = o[dj][0] * inv0, y1 = o[dj][1] * inv0;
        float y2 = o[dj][2] * inv1, y3 = o[dj][3] * inv1;
        __half2 hA = __floats2half2_rn(y0, y1);
        float2 fA = __half22float2(hA);
        __half2 lA = __floats2half2_rn(y0 - fA.x, y1 - fA.y);
        __half2 hB = __floats2half2_rn(y2, y3);
        float2 fB = __half22float2(hB);
        __half2 lB = __floats2half2_rn(y2 - fB.x, y3 - fB.y);
        *(__half2*)(Yh + row0 * DMODEL + col)       = hA;
        *(__half2*)(Yl + row0 * DMODEL + col)       = lA;
        *(__half2*)(Yh + (row0 + 8) * DMODEL + col) = hB;
        *(__half2*)(Yl + (row0 + 8) * DMODEL + col) = lB;
    }
}

// ---------------------------------------------------------------------------
extern "C" void kernel_launch(void* const* d_in, const int* in_sizes, int n_in,
                              void* d_out, int out_size)
{
    (void)in_sizes; (void)n_in; (void)out_size;
    const float* x     = (const float*)d_in[0];
    const float* Wq    = (const float*)d_in[1];
    const float* Wkv   = (const float*)d_in[2];
    const float* Wproj = (const float*)d_in[3];
    float* out = (float*)d_out;

    float *q_ptr, *kv_ptr;
    cudaGetSymbolAddress((void**)&q_ptr,  g_q);
    cudaGetSymbolAddress((void**)&kv_ptr, g_kv);
    __half *xh, *xl, *wqh, *wkh, *wph, *qh, *ql, *kvh, *yh, *yl;
    cudaGetSymbolAddress((void**)&xh,  g_xh);  cudaGetSymbolAddress((void**)&xl,  g_xl);
    cudaGetSymbolAddress((void**)&wqh, g_wqh);
    cudaGetSymbolAddress((void**)&wkh, g_wkh);
    cudaGetSymbolAddress((void**)&wph, g_wph);
    cudaGetSymbolAddress((void**)&qh,  g_qh);  cudaGetSymbolAddress((void**)&ql,  g_ql);
    cudaGetSymbolAddress((void**)&kvh, g_kvh);
    cudaGetSymbolAddress((void**)&yh,  g_yh);  cudaGetSymbolAddress((void**)&yl,  g_yl);

    cudaFuncSetAttribute(gemm_mma, cudaFuncAttributeMaxDynamicSharedMemorySize, G_SMEM);
    cudaFuncSetAttribute(attn_mma, cudaFuncAttributeMaxDynamicSharedMemorySize, A_SMEM);

    // 0) input conversions
    {
        int n;
        n = MTOT * DMODEL / 4;   split_kernel<<<n / 256, 256>>>(x, xh, xl, n);
        n = DMODEL * DMODEL / 4; cvt_kernel<<<n / 256, 256>>>(Wq,    wqh, n);
        n = KVDIM * DMODEL / 4;  cvt_kernel<<<n / 256, 256>>>(Wkv,   wkh, n);
        n = DMODEL * DMODEL / 4; cvt_kernel<<<n / 256, 256>>>(Wproj, wph, n);
    }

    // 1) Q = x Wq^T ; 2) KV = x Wkv^T
    gemm_mma<<<dim3(DMODEL / 128, MTOT / 128), 256, G_SMEM>>>(xh, xl, wqh, q_ptr,
                                                              MTOT, DMODEL, DMODEL);
    gemm_mma<<<dim3(KVDIM / 128,  MTOT / 128), 256, G_SMEM>>>(xh, xl, wkh, kv_ptr,
                                                              MTOT, KVDIM, DMODEL);

    // 3) rope+split q; cvt kv then rope-overwrite k half
    {
        int total_q = MTOT * NHEAD * (HDIM / 2);
        rope_split<<<(total_q + 255) / 256, 256>>>(q_ptr, qh, ql, DMODEL, NHEAD);
        int n = MTOT * KVDIM / 4;
        cvt_kernel<<<n / 256, 256>>>(kv_ptr, kvh, n);
        int total_k = MTOT * NKV * (HDIM / 2);
        rope_cvt<<<(total_k + 255) / 256, 256>>>(kv_ptr, kvh, KVDIM, NKV);
    }

    // 4) attention -> yh/yl
    attn_mma<<<dim3(SEQ / 128, BATCH * NHEAD), 256, A_SMEM>>>(qh, ql, kvh, yh, yl);

    // 5) out = y Wproj^T
    gemm_mma<<<dim3(DMODEL / 128, MTOT / 128), 256, G_SMEM>>>(yh, yl, wph, out,
                                                              MTOT, DMODEL, DMODEL);
}

// round 6
// speedup vs baseline: 7.3593x; 1.6640x over previous
#include <cuda_runtime.h>
#include <cuda_fp16.h>
#include <cstdint>
#include <math.h>

#define BATCH  2
#define SEQ    2048
#define DMODEL 2048
#define NHEAD  16
#define NKV    4
#define HDIM   128
#define KVDIM  1024
#define MTOT   4096

// ---------------- scratch ----------------
__device__ float g_q [(size_t)MTOT * DMODEL];
__device__ float g_kv[(size_t)MTOT * KVDIM];

__device__ __half g_xh [(size_t)MTOT * DMODEL];
__device__ __half g_wqh[(size_t)DMODEL * DMODEL];
__device__ __half g_wkh[(size_t)KVDIM * DMODEL];
__device__ __half g_wph[(size_t)DMODEL * DMODEL];
__device__ __half g_qh [(size_t)MTOT * DMODEL];
__device__ __half g_kvh[(size_t)MTOT * KVDIM];
__device__ __half g_yh [(size_t)MTOT * DMODEL];

// ---------------- helpers ----------------
__device__ __forceinline__ uint32_t smem_u32(const void* p) {
    uint32_t a;
    asm("{ .reg .u64 t; cvta.to.shared.u64 t, %1; cvt.u32.u64 %0, t; }" : "=r"(a) : "l"(p));
    return a;
}
__device__ __forceinline__ void ldsm_x4(uint32_t* r, uint32_t addr) {
    asm volatile("ldmatrix.sync.aligned.m8n8.x4.shared.b16 {%0,%1,%2,%3}, [%4];"
                 : "=r"(r[0]), "=r"(r[1]), "=r"(r[2]), "=r"(r[3]) : "r"(addr));
}
__device__ __forceinline__ void ldsm_x4_t(uint32_t* r, uint32_t addr) {
    asm volatile("ldmatrix.sync.aligned.m8n8.x4.trans.shared.b16 {%0,%1,%2,%3}, [%4];"
                 : "=r"(r[0]), "=r"(r[1]), "=r"(r[2]), "=r"(r[3]) : "r"(addr));
}
__device__ __forceinline__ void mma_f16(float* d, const uint32_t* a, const uint32_t* b) {
    asm volatile(
        "mma.sync.aligned.m16n8k16.row.col.f32.f16.f16.f32 "
        "{%0,%1,%2,%3}, {%4,%5,%6,%7}, {%8,%9}, {%0,%1,%2,%3};"
        : "+f"(d[0]), "+f"(d[1]), "+f"(d[2]), "+f"(d[3])
        : "r"(a[0]), "r"(a[1]), "r"(a[2]), "r"(a[3]), "r"(b[0]), "r"(b[1]));
}
__device__ __forceinline__ uint32_t h2_as_u32(__half2 v) {
    return *reinterpret_cast<uint32_t*>(&v);
}
__device__ __forceinline__ void cp_async16(uint32_t dst, const void* src) {
    asm volatile("cp.async.cg.shared.global [%0], [%1], 16;" :: "r"(dst), "l"(src));
}
__device__ __forceinline__ void cp_commit() {
    asm volatile("cp.async.commit_group;" ::: "memory");
}
template <int N>
__device__ __forceinline__ void cp_wait() {
    asm volatile("cp.async.wait_group %0;" :: "n"(N) : "memory");
}

// ---------------- fp32 -> fp16 ----------------
__global__ void cvt_kernel(const float* __restrict__ src,
                           __half* __restrict__ dst, int n4)
{
    int i = blockIdx.x * blockDim.x + threadIdx.x;
    if (i >= n4) return;
    float4 v = ((const float4*)src)[i];
    union { __half b[4]; uint2 u; } H;
    H.b[0] = __float2half_rn(v.x); H.b[1] = __float2half_rn(v.y);
    H.b[2] = __float2half_rn(v.z); H.b[3] = __float2half_rn(v.w);
    ((uint2*)dst)[i] = H.u;
}

// ---------------- RoPE -> fp16 ----------------
__global__ void rope_cvt(const float* __restrict__ buf,
                         __half* __restrict__ hi,
                         int rowstride, int nheads)
{
    int idx = blockIdx.x * blockDim.x + threadIdx.x;
    int total = MTOT * nheads * (HDIM / 2);
    if (idx >= total) return;
    int j = idx & 63;
    int h = (idx >> 6) % nheads;
    int m = idx / (64 * nheads);
    int t = m & (SEQ - 1);
    float freq = powf(10000.0f, (float)j * (1.0f / 64.0f));
    float ang  = (float)t / freq;
    float s, c;
    sincosf(ang, &s, &c);
    size_t o = (size_t)m * rowstride + h * HDIM;
    float x1 = buf[o + j], x2 = buf[o + j + 64];
    hi[o + j]      = __float2half_rn(x1 * c - x2 * s);
    hi[o + j + 64] = __float2half_rn(x2 * c + x1 * s);
}

// ---------------------------------------------------------------------------
// HMMA fp16 NT GEMM: C = A B^T, fp32 accum/out.
// CTA 128x128, BK=32, 8 warps (4m x 2n), cp.async 3-stage, 2 CTA/SM.
// ---------------------------------------------------------------------------
#define GBK     32
#define G_ROWB  80
#define G_TILEB (128 * G_ROWB)     // 10240
#define G_STGB  (2 * G_TILEB)      // 20480 (A, B)
#define G_SMEM  (3 * G_STGB)       // 61440

__global__ __launch_bounds__(256, 2)
void gemm_mma(const __half* __restrict__ A, const __half* __restrict__ B,
              float* __restrict__ C, int M, int N, int K)
{
    extern __shared__ char smem[];
    const uint32_t sb0 = smem_u32(smem);
    const int tid = threadIdx.x, l = tid & 31, wid = tid >> 5;
    const int wm = wid & 3, wn = wid >> 2;
    const int mbase = blockIdx.y * 128, nbase = blockIdx.x * 128;

    const int g_row0 = tid >> 2, g_c = tid & 3;
    const int g_row1 = g_row0 + 64;

    const uint32_t laA = (uint32_t)((l & 15) * G_ROWB + (l >> 4) * 16);
    const uint32_t laB = (uint32_t)(((((l >> 4) << 3) | (l & 7)) * G_ROWB) + (((l >> 3) & 1) * 16));

    float acc[2][8][4] = {};

    auto issue = [&](int kb, int stg) {
        const uint32_t sb = sb0 + (uint32_t)stg * G_STGB;
        const uint32_t o0 = (uint32_t)(g_row0 * G_ROWB + g_c * 16);
        const uint32_t o1 = (uint32_t)(g_row1 * G_ROWB + g_c * 16);
        size_t a0 = (size_t)(mbase + g_row0) * K + kb + g_c * 8;
        size_t a1 = (size_t)(mbase + g_row1) * K + kb + g_c * 8;
        size_t b0 = (size_t)(nbase + g_row0) * K + kb + g_c * 8;
        size_t b1 = (size_t)(nbase + g_row1) * K + kb + g_c * 8;
        cp_async16(sb + 0 * G_TILEB + o0, A + a0);
        cp_async16(sb + 0 * G_TILEB + o1, A + a1);
        cp_async16(sb + 1 * G_TILEB + o0, B + b0);
        cp_async16(sb + 1 * G_TILEB + o1, B + b1);
    };

    const int NC = K / GBK;
    issue(0, 0); cp_commit();
    issue(GBK, 1); cp_commit();

    int stg = 0;
    for (int i = 0; i < NC; i++) {
        cp_wait<1>();
        __syncthreads();
        // stage (i+2)%3: always commit (possibly empty) to keep group bookkeeping uniform
        {
            int s2 = stg + 2; if (s2 >= 3) s2 -= 3;
            if (i + 2 < NC) issue((i + 2) * GBK, s2);
            cp_commit();
        }

        const uint32_t base = sb0 + (uint32_t)stg * G_STGB;
        const uint32_t sA = base, sB = base + G_TILEB;
        #pragma unroll
        for (int ks = 0; ks < 2; ks++) {
            const uint32_t koff = ks * 32;
            uint32_t af[2][4];
            #pragma unroll
            for (int mi = 0; mi < 2; mi++) {
                uint32_t ra = (uint32_t)((wm * 32 + mi * 16) * G_ROWB) + koff + laA;
                ldsm_x4(af[mi], sA + ra);
            }
            #pragma unroll
            for (int nj2 = 0; nj2 < 4; nj2++) {
                uint32_t rb = (uint32_t)(((wn * 64) + nj2 * 16) * G_ROWB) + koff + laB;
                uint32_t bf[4];
                ldsm_x4(bf, sB + rb);
                #pragma unroll
                for (int mi = 0; mi < 2; mi++) {
                    mma_f16(acc[mi][2 * nj2],     af[mi], bf);
                    mma_f16(acc[mi][2 * nj2 + 1], af[mi], bf + 2);
                }
            }
        }
        if (++stg == 3) stg = 0;
    }

    #pragma unroll
    for (int mi = 0; mi < 2; mi++) {
        int row = mbase + wm * 32 + mi * 16 + (l >> 2);
        #pragma unroll
        for (int nj = 0; nj < 8; nj++) {
            int col = nbase + wn * 64 + nj * 8 + (l & 3) * 2;
            *(float2*)&C[(size_t)row * N + col]       = make_float2(acc[mi][nj][0], acc[mi][nj][1]);
            *(float2*)&C[(size_t)(row + 8) * N + col] = make_float2(acc[mi][nj][2], acc[mi][nj][3]);
        }
    }
}

// ---------------------------------------------------------------------------
// HMMA fp16 flash attention, causal, GQA; cp.async double-buffered KV; 2 CTA/SM.
// ---------------------------------------------------------------------------
#define AQROWB  272
#define AQTILEB (128 * AQROWB)       // 34816
#define AKTILEB (64 * AQROWB)        // 17408
#define A_SQ    0
#define A_KV    (A_SQ + AQTILEB)     // 34816
#define A_KVSTG (2 * AKTILEB)        // 34816 (K, V)
#define A_SMEM  (A_KV + 2 * A_KVSTG) // 104448

__global__ __launch_bounds__(256, 2)
void attn_mma(const __half* __restrict__ Qh, const __half* __restrict__ KVh,
              __half* __restrict__ Yh)
{
    extern __shared__ char smem[];
    const uint32_t sb = smem_u32(smem);
    const int tid = threadIdx.x, l = tid & 31, wid = tid >> 5;
    const int qtile = gridDim.x - 1 - blockIdx.x;      // heavy tiles first
    const int bhidx = blockIdx.y;
    const int b = bhidx >> 4, h = bhidx & 15, kvh = h >> 2;
    const int qbase = qtile * 128;

    const __half* kp = KVh + (size_t)(b * SEQ) * KVDIM + kvh * HDIM;

    auto issue_kv = [&](int kbase, int stg) {
        const uint32_t sbase = sb + A_KV + (uint32_t)stg * A_KVSTG;
        #pragma unroll
        for (int j = 0; j < 4; j++) {
            int s = tid + j * 256;
            int row = s >> 4, c = s & 15;
            size_t src = (size_t)(kbase + row) * KVDIM + c * 8;
            uint32_t dst = (uint32_t)(row * AQROWB + c * 16);
            cp_async16(sbase + 0 * AKTILEB + dst, kp + src);          // K
            cp_async16(sbase + 1 * AKTILEB + dst, kp + src + 512);    // V
        }
    };

    // Q tile load (once)
    {
        const __half* qh = Qh + ((size_t)(b * SEQ + qbase)) * DMODEL + h * HDIM;
        #pragma unroll
        for (int j = 0; j < 8; j++) {
            int s = tid + j * 256;
            int row = s >> 4, c = s & 15;
            size_t src = (size_t)row * DMODEL + c * 8;
            uint32_t dst = (uint32_t)(row * AQROWB + c * 16);
            *(uint4*)(smem + A_SQ + dst) = *(const uint4*)(qh + src);
        }
    }

    issue_kv(0, 0);
    cp_commit();

    const uint32_t laA = (uint32_t)((l & 15) * AQROWB + (l >> 4) * 16);
    const uint32_t laB = (uint32_t)(((((l >> 4) << 3) | (l & 7)) * AQROWB) + (((l >> 3) & 1) * 16));
    const uint32_t laV = (uint32_t)(((((l >> 3) & 1) * 8 + (l & 7)) * AQROWB) + ((l >> 4) * 16));

    float o[16][4] = {};
    float rm0 = -1e30f, rm1 = -1e30f, lp0 = 0.f, lp1 = 0.f;
    const float scale = 0.08838834764831845f;
    const int ktiles = 2 * qtile + 2;

    for (int kt = 0; kt < ktiles; kt++) {
        const int kbase = kt * 64;
        cp_wait<0>();
        __syncthreads();
        if (kt + 1 < ktiles) { issue_kv((kt + 1) * 64, (kt + 1) & 1); cp_commit(); }

        const uint32_t kvb = sb + A_KV + (uint32_t)(kt & 1) * A_KVSTG;
        const uint32_t sKH = kvb, sVH = kvb + AKTILEB;

        // ---- S = Q K^T ----
        float s_[8][4] = {};
        #pragma unroll
        for (int ks = 0; ks < 8; ks++) {
            const uint32_t koff = ks * 32;
            uint32_t aq[4];
            uint32_t ra = (uint32_t)((wid * 16) * AQROWB) + koff;
            ldsm_x4(aq, sb + A_SQ + ra + laA);
            #pragma unroll
            for (int nj2 = 0; nj2 < 4; nj2++) {
                uint32_t rb = (uint32_t)((nj2 * 16) * AQROWB) + koff + laB;
                uint32_t th[4];
                ldsm_x4(th, sKH + rb);
                mma_f16(s_[2 * nj2],     aq, th);
                mma_f16(s_[2 * nj2 + 1], aq, th + 2);
            }
        }

        // ---- scale + causal mask ----
        const int qrow0 = qbase + wid * 16 + (l >> 2);
        #pragma unroll
        for (int nj = 0; nj < 8; nj++)
            #pragma unroll
            for (int c = 0; c < 4; c++) s_[nj][c] *= scale;
        if (kbase + 63 > qbase + wid * 16) {
            #pragma unroll
            for (int nj = 0; nj < 8; nj++) {
                int kp2 = kbase + nj * 8 + (l & 3) * 2;
                if (kp2     > qrow0)     s_[nj][0] = -1e30f;
                if (kp2 + 1 > qrow0)     s_[nj][1] = -1e30f;
                if (kp2     > qrow0 + 8) s_[nj][2] = -1e30f;
                if (kp2 + 1 > qrow0 + 8) s_[nj][3] = -1e30f;
            }
        }

        // ---- online softmax ----
        float mx0 = -1e30f, mx1 = -1e30f;
        #pragma unroll
        for (int nj = 0; nj < 8; nj++) {
            mx0 = fmaxf(mx0, fmaxf(s_[nj][0], s_[nj][1]));
            mx1 = fmaxf(mx1, fmaxf(s_[nj][2], s_[nj][3]));
        }
        mx0 = fmaxf(mx0, __shfl_xor_sync(0xffffffffu, mx0, 1));
        mx0 = fmaxf(mx0, __shfl_xor_sync(0xffffffffu, mx0, 2));
        mx1 = fmaxf(mx1, __shfl_xor_sync(0xffffffffu, mx1, 1));
        mx1 = fmaxf(mx1, __shfl_xor_sync(0xffffffffu, mx1, 2));
        float nm0 = fmaxf(rm0, mx0), nm1 = fmaxf(rm1, mx1);
        float al0 = __expf(rm0 - nm0), al1 = __expf(rm1 - nm1);
        rm0 = nm0; rm1 = nm1;
        float ps0 = 0.f, ps1 = 0.f;
        #pragma unroll
        for (int nj = 0; nj < 8; nj++) {
            s_[nj][0] = __expf(s_[nj][0] - nm0);
            s_[nj][1] = __expf(s_[nj][1] - nm0);
            s_[nj][2] = __expf(s_[nj][2] - nm1);
            s_[nj][3] = __expf(s_[nj][3] - nm1);
            ps0 += s_[nj][0] + s_[nj][1];
            ps1 += s_[nj][2] + s_[nj][3];
        }
        lp0 = lp0 * al0 + ps0;
        lp1 = lp1 * al1 + ps1;
        #pragma unroll
        for (int dj = 0; dj < 16; dj++) {
            o[dj][0] *= al0; o[dj][1] *= al0;
            o[dj][2] *= al1; o[dj][3] *= al1;
        }

        // ---- O += P V ----
        #pragma unroll
        for (int kks = 0; kks < 4; kks++) {
            uint32_t ap[4];
            {
                const float* p0 = s_[2 * kks];
                const float* p1 = s_[2 * kks + 1];
                ap[0] = h2_as_u32(__floats2half2_rn(p0[0], p0[1]));
                ap[1] = h2_as_u32(__floats2half2_rn(p0[2], p0[3]));
                ap[2] = h2_as_u32(__floats2half2_rn(p1[0], p1[1]));
                ap[3] = h2_as_u32(__floats2half2_rn(p1[2], p1[3]));
            }
            uint32_t rvb = (uint32_t)((kks * 16) * AQROWB) + laV;
            #pragma unroll
            for (int dj2 = 0; dj2 < 8; dj2++) {
                uint32_t coff = dj2 * 32;
                uint32_t tv[4];
                ldsm_x4_t(tv, sVH + rvb + coff);
                mma_f16(o[2 * dj2],     ap, tv);
                mma_f16(o[2 * dj2 + 1], ap, tv + 2);
            }
        }
    }

    // ---- finalize ----
    lp0 += __shfl_xor_sync(0xffffffffu, lp0, 1);
    lp0 += __shfl_xor_sync(0xffffffffu, lp0, 2);
    lp1 += __shfl_xor_sync(0xffffffffu, lp1, 1);
    lp1 += __shfl_xor_sync(0xffffffffu, lp1, 2);
    float inv0 = 1.0f / lp0, inv1 = 1.0f / lp1;

    const size_t row0 = (size_t)(b * SEQ + qbase + wid * 16 + (l >> 2));
    const int colb = h * HDIM + (l & 3) * 2;
    #pragma unroll
    for (int dj = 0; dj < 16; dj++) {
        int col = colb + dj * 8;
        *(__half2*)(Yh + row0 * DMODEL + col) =
            __floats2half2_rn(o[dj][0] * inv0, o[dj][1] * inv0);
        *(__half2*)(Yh + (row0 + 8) * DMODEL + col) =
            __floats2half2_rn(o[dj][2] * inv1, o[dj][3] * inv1);
    }
}

// ---------------------------------------------------------------------------
extern "C" void kernel_launch(void* const* d_in, const int* in_sizes, int n_in,
                              void* d_out, int out_size)
{
    (void)in_sizes; (void)n_in; (void)out_size;
    const float* x     = (const float*)d_in[0];
    const float* Wq    = (const float*)d_in[1];
    const float* Wkv   = (const float*)d_in[2];
    const float* Wproj = (const float*)d_in[3];
    float* out = (float*)d_out;

    float *q_ptr, *kv_ptr;
    cudaGetSymbolAddress((void**)&q_ptr,  g_q);
    cudaGetSymbolAddress((void**)&kv_ptr, g_kv);
    __half *xh, *wqh, *wkh, *wph, *qh, *kvh, *yh;
    cudaGetSymbolAddress((void**)&xh,  g_xh);
    cudaGetSymbolAddress((void**)&wqh, g_wqh);
    cudaGetSymbolAddress((void**)&wkh, g_wkh);
    cudaGetSymbolAddress((void**)&wph, g_wph);
    cudaGetSymbolAddress((void**)&qh,  g_qh);
    cudaGetSymbolAddress((void**)&kvh, g_kvh);
    cudaGetSymbolAddress((void**)&yh,  g_yh);

    cudaFuncSetAttribute(gemm_mma, cudaFuncAttributeMaxDynamicSharedMemorySize, G_SMEM);
    cudaFuncSetAttribute(attn_mma, cudaFuncAttributeMaxDynamicSharedMemorySize, A_SMEM);

    // 0) input conversions
    {
        int n;
        n = MTOT * DMODEL / 4;   cvt_kernel<<<n / 256, 256>>>(x,     xh,  n);
        n = DMODEL * DMODEL / 4; cvt_kernel<<<n / 256, 256>>>(Wq,    wqh, n);
        n = KVDIM * DMODEL / 4;  cvt_kernel<<<n / 256, 256>>>(Wkv,   wkh, n);
        n = DMODEL * DMODEL / 4; cvt_kernel<<<n / 256, 256>>>(Wproj, wph, n);
    }

    // 1) Q = x Wq^T ; 2) KV = x Wkv^T   (fp32 out)
    gemm_mma<<<dim3(DMODEL / 128, MTOT / 128), 256, G_SMEM>>>(xh, wqh, q_ptr,
                                                              MTOT, DMODEL, DMODEL);
    gemm_mma<<<dim3(KVDIM / 128,  MTOT / 128), 256, G_SMEM>>>(xh, wkh, kv_ptr,
                                                              MTOT, KVDIM, DMODEL);

    // 3) rope->fp16 for q; cvt kv then rope-overwrite k half
    {
        int total_q = MTOT * NHEAD * (HDIM / 2);
        rope_cvt<<<(total_q + 255) / 256, 256>>>(q_ptr, qh, DMODEL, NHEAD);
        int n = MTOT * KVDIM / 4;
        cvt_kernel<<<n / 256, 256>>>(kv_ptr, kvh, n);
        int total_k = MTOT * NKV * (HDIM / 2);
        rope_cvt<<<(total_k + 255) / 256, 256>>>(kv_ptr, kvh, KVDIM, NKV);
    }

    // 4) attention -> yh (fp16)
    attn_mma<<<dim3(SEQ / 128, BATCH * NHEAD), 256, A_SMEM>>>(qh, kvh, yh);

    // 5) out = y Wproj^T
    gemm_mma<<<dim3(DMODEL / 128, MTOT / 128), 256, G_SMEM>>>(yh, wph, out,
                                                              MTOT, DMODEL, DMODEL);
}

// round 7
// speedup vs baseline: 8.0275x; 1.0908x over previous
#include <cuda_runtime.h>
#include <cuda_fp16.h>
#include <cstdint>
#include <math.h>

#define BATCH  2
#define SEQ    2048
#define DMODEL 2048
#define NHEAD  16
#define NKV    4
#define HDIM   128
#define KVDIM  1024
#define QKVW   3072            // fused q|k|v row width
#define MTOT   4096

// ---------------- scratch ----------------
__device__ __half g_xh  [(size_t)MTOT * DMODEL];
__device__ __half g_wh  [(size_t)QKVW * DMODEL];     // [Wq; Wkv] fp16
__device__ __half g_wph [(size_t)DMODEL * DMODEL];
__device__ __half g_qkvh[(size_t)MTOT * QKVW];       // fused q|k|v fp16
__device__ __half g_yh  [(size_t)MTOT * DMODEL];

// ---------------- helpers ----------------
__device__ __forceinline__ uint32_t smem_u32(const void* p) {
    uint32_t a;
    asm("{ .reg .u64 t; cvta.to.shared.u64 t, %1; cvt.u32.u64 %0, t; }" : "=r"(a) : "l"(p));
    return a;
}
__device__ __forceinline__ void ldsm_x4(uint32_t* r, uint32_t addr) {
    asm volatile("ldmatrix.sync.aligned.m8n8.x4.shared.b16 {%0,%1,%2,%3}, [%4];"
                 : "=r"(r[0]), "=r"(r[1]), "=r"(r[2]), "=r"(r[3]) : "r"(addr));
}
__device__ __forceinline__ void ldsm_x4_t(uint32_t* r, uint32_t addr) {
    asm volatile("ldmatrix.sync.aligned.m8n8.x4.trans.shared.b16 {%0,%1,%2,%3}, [%4];"
                 : "=r"(r[0]), "=r"(r[1]), "=r"(r[2]), "=r"(r[3]) : "r"(addr));
}
__device__ __forceinline__ void mma_f16(float* d, const uint32_t* a, const uint32_t* b) {
    asm volatile(
        "mma.sync.aligned.m16n8k16.row.col.f32.f16.f16.f32 "
        "{%0,%1,%2,%3}, {%4,%5,%6,%7}, {%8,%9}, {%0,%1,%2,%3};"
        : "+f"(d[0]), "+f"(d[1]), "+f"(d[2]), "+f"(d[3])
        : "r"(a[0]), "r"(a[1]), "r"(a[2]), "r"(a[3]), "r"(b[0]), "r"(b[1]));
}
__device__ __forceinline__ uint32_t h2_as_u32(__half2 v) {
    return *reinterpret_cast<uint32_t*>(&v);
}
__device__ __forceinline__ void cp_async16(uint32_t dst, const void* src) {
    asm volatile("cp.async.cg.shared.global [%0], [%1], 16;" :: "r"(dst), "l"(src));
}
__device__ __forceinline__ void cp_commit() {
    asm volatile("cp.async.commit_group;" ::: "memory");
}
template <int N>
__device__ __forceinline__ void cp_wait() {
    asm volatile("cp.async.wait_group %0;" :: "n"(N) : "memory");
}

// ---------------- fp32 -> fp16 ----------------
__global__ void cvt_kernel(const float* __restrict__ src,
                           __half* __restrict__ dst, int n4)
{
    int i = blockIdx.x * blockDim.x + threadIdx.x;
    if (i >= n4) return;
    float4 v = ((const float4*)src)[i];
    union { __half b[4]; uint2 u; } H;
    H.b[0] = __float2half_rn(v.x); H.b[1] = __float2half_rn(v.y);
    H.b[2] = __float2half_rn(v.z); H.b[3] = __float2half_rn(v.w);
    ((uint2*)dst)[i] = H.u;
}

// ---------------- in-place fp16 RoPE over heads 0..nheads-1 ----------------
__global__ void rope16(__half* __restrict__ buf, int rowstride, int nheads)
{
    int idx = blockIdx.x * blockDim.x + threadIdx.x;
    int total = MTOT * nheads * (HDIM / 2);
    if (idx >= total) return;
    int j = idx & 63;
    int h = (idx >> 6) % nheads;
    int m = idx / (64 * nheads);
    int t = m & (SEQ - 1);
    float freq = powf(10000.0f, (float)j * (1.0f / 64.0f));
    float ang  = (float)t / freq;
    float s, c;
    sincosf(ang, &s, &c);
    size_t o = (size_t)m * rowstride + h * HDIM;
    float x1 = __half2float(buf[o + j]);
    float x2 = __half2float(buf[o + j + 64]);
    buf[o + j]      = __float2half_rn(x1 * c - x2 * s);
    buf[o + j + 64] = __float2half_rn(x2 * c + x1 * s);
}

// ---------------------------------------------------------------------------
// HMMA fp16 NT GEMM: C = A B^T. fp32 accum; output fp16 or fp32 (template).
// CTA 128x128, BK=32, 8 warps (4m x 2n), cp.async 3-stage, 2 CTA/SM.
// ---------------------------------------------------------------------------
#define GBK     32
#define G_ROWB  80
#define G_TILEB (128 * G_ROWB)     // 10240
#define G_STGB  (2 * G_TILEB)      // 20480
#define G_SMEM  (3 * G_STGB)       // 61440

template <bool HALF_OUT>
__global__ __launch_bounds__(256, 2)
void gemm_mma(const __half* __restrict__ A, const __half* __restrict__ B,
              void* __restrict__ Cv, int M, int N, int K)
{
    extern __shared__ char smem[];
    const uint32_t sb0 = smem_u32(smem);
    const int tid = threadIdx.x, l = tid & 31, wid = tid >> 5;
    const int wm = wid & 3, wn = wid >> 2;
    const int mbase = blockIdx.y * 128, nbase = blockIdx.x * 128;

    const int g_row0 = tid >> 2, g_c = tid & 3;
    const int g_row1 = g_row0 + 64;

    const uint32_t laA = (uint32_t)((l & 15) * G_ROWB + (l >> 4) * 16);
    const uint32_t laB = (uint32_t)(((((l >> 4) << 3) | (l & 7)) * G_ROWB) + (((l >> 3) & 1) * 16));

    float acc[2][8][4] = {};

    auto issue = [&](int kb, int stg) {
        const uint32_t sb = sb0 + (uint32_t)stg * G_STGB;
        const uint32_t o0 = (uint32_t)(g_row0 * G_ROWB + g_c * 16);
        const uint32_t o1 = (uint32_t)(g_row1 * G_ROWB + g_c * 16);
        size_t a0 = (size_t)(mbase + g_row0) * K + kb + g_c * 8;
        size_t a1 = (size_t)(mbase + g_row1) * K + kb + g_c * 8;
        size_t b0 = (size_t)(nbase + g_row0) * K + kb + g_c * 8;
        size_t b1 = (size_t)(nbase + g_row1) * K + kb + g_c * 8;
        cp_async16(sb + 0 * G_TILEB + o0, A + a0);
        cp_async16(sb + 0 * G_TILEB + o1, A + a1);
        cp_async16(sb + 1 * G_TILEB + o0, B + b0);
        cp_async16(sb + 1 * G_TILEB + o1, B + b1);
    };

    const int NC = K / GBK;
    issue(0, 0); cp_commit();
    issue(GBK, 1); cp_commit();

    int stg = 0;
    for (int i = 0; i < NC; i++) {
        cp_wait<1>();
        __syncthreads();
        {
            int s2 = stg + 2; if (s2 >= 3) s2 -= 3;
            if (i + 2 < NC) issue((i + 2) * GBK, s2);
            cp_commit();
        }

        const uint32_t base = sb0 + (uint32_t)stg * G_STGB;
        const uint32_t sA = base, sB = base + G_TILEB;
        #pragma unroll
        for (int ks = 0; ks < 2; ks++) {
            const uint32_t koff = ks * 32;
            uint32_t af[2][4];
            #pragma unroll
            for (int mi = 0; mi < 2; mi++) {
                uint32_t ra = (uint32_t)((wm * 32 + mi * 16) * G_ROWB) + koff + laA;
                ldsm_x4(af[mi], sA + ra);
            }
            #pragma unroll
            for (int nj2 = 0; nj2 < 4; nj2++) {
                uint32_t rb = (uint32_t)(((wn * 64) + nj2 * 16) * G_ROWB) + koff + laB;
                uint32_t bf[4];
                ldsm_x4(bf, sB + rb);
                #pragma unroll
                for (int mi = 0; mi < 2; mi++) {
                    mma_f16(acc[mi][2 * nj2],     af[mi], bf);
                    mma_f16(acc[mi][2 * nj2 + 1], af[mi], bf + 2);
                }
            }
        }
        if (++stg == 3) stg = 0;
    }

    #pragma unroll
    for (int mi = 0; mi < 2; mi++) {
        int row = mbase + wm * 32 + mi * 16 + (l >> 2);
        #pragma unroll
        for (int nj = 0; nj < 8; nj++) {
            int col = nbase + wn * 64 + nj * 8 + (l & 3) * 2;
            if (HALF_OUT) {
                __half* C = (__half*)Cv;
                *(__half2*)&C[(size_t)row * N + col] =
                    __floats2half2_rn(acc[mi][nj][0], acc[mi][nj][1]);
                *(__half2*)&C[(size_t)(row + 8) * N + col] =
                    __floats2half2_rn(acc[mi][nj][2], acc[mi][nj][3]);
            } else {
                float* C = (float*)Cv;
                *(float2*)&C[(size_t)row * N + col] =
                    make_float2(acc[mi][nj][0], acc[mi][nj][1]);
                *(float2*)&C[(size_t)(row + 8) * N + col] =
                    make_float2(acc[mi][nj][2], acc[mi][nj][3]);
            }
        }
    }
}

// ---------------------------------------------------------------------------
// HMMA fp16 flash attention, causal, GQA; fused QKV input (row stride 3072).
// Grid (8, 32): each CTA does qtile pair (i, 15-i) -> 36 kv-tiles per CTA,
// one balanced wave of 256 CTAs at 2 CTA/SM.
// ---------------------------------------------------------------------------
#define AQROWB  272
#define AQTILEB (128 * AQROWB)       // 34816
#define AKTILEB (64 * AQROWB)        // 17408
#define A_SQ    0
#define A_KV    (A_SQ + AQTILEB)
#define A_KVSTG (2 * AKTILEB)
#define A_SMEM  (A_KV + 2 * A_KVSTG) // 104448

#define SCALE_LOG2E 0.12751589542466683f   // (1/sqrt(128)) * log2(e)

__global__ __launch_bounds__(256, 2)
void attn_mma(const __half* __restrict__ QKV, __half* __restrict__ Yh)
{
    extern __shared__ char smem[];
    const uint32_t sb = smem_u32(smem);
    const int tid = threadIdx.x, l = tid & 31, wid = tid >> 5;
    const int bhidx = blockIdx.y;
    const int b = bhidx >> 4, h = bhidx & 15, kvh = h >> 2;

    const __half* kp = QKV + (size_t)(b * SEQ) * QKVW + DMODEL + kvh * HDIM;

    auto issue_kv = [&](int kbase, int stg) {
        const uint32_t sbase = sb + A_KV + (uint32_t)stg * A_KVSTG;
        #pragma unroll
        for (int j = 0; j < 4; j++) {
            int s = tid + j * 256;
            int row = s >> 4, c = s & 15;
            size_t src = (size_t)(kbase + row) * QKVW + c * 8;
            uint32_t dst = (uint32_t)(row * AQROWB + c * 16);
            cp_async16(sbase + 0 * AKTILEB + dst, kp + src);          // K
            cp_async16(sbase + 1 * AKTILEB + dst, kp + src + 512);    // V
        }
    };

    const uint32_t laA = (uint32_t)((l & 15) * AQROWB + (l >> 4) * 16);
    const uint32_t laB = (uint32_t)(((((l >> 4) << 3) | (l & 7)) * AQROWB) + (((l >> 3) & 1) * 16));
    const uint32_t laV = (uint32_t)(((((l >> 3) & 1) * 8 + (l & 7)) * AQROWB) + ((l >> 4) * 16));

    #pragma unroll 1
    for (int pass = 0; pass < 2; pass++) {
        const int qtile = pass == 0 ? (int)blockIdx.x : (int)(15 - blockIdx.x);
        const int qbase = qtile * 128;

        __syncthreads();   // previous pass finished all smem reads

        // Q tile load
        {
            const __half* qh = QKV + ((size_t)(b * SEQ + qbase)) * QKVW + h * HDIM;
            #pragma unroll
            for (int j = 0; j < 8; j++) {
                int s = tid + j * 256;
                int row = s >> 4, c = s & 15;
                size_t src = (size_t)row * QKVW + c * 8;
                uint32_t dst = (uint32_t)(row * AQROWB + c * 16);
                *(uint4*)(smem + A_SQ + dst) = *(const uint4*)(qh + src);
            }
        }

        issue_kv(0, 0);
        cp_commit();

        float o[16][4] = {};
        float rm0 = -1e30f, rm1 = -1e30f, lp0 = 0.f, lp1 = 0.f;
        const int ktiles = 2 * qtile + 2;

        for (int kt = 0; kt < ktiles; kt++) {
            const int kbase = kt * 64;
            cp_wait<0>();
            __syncthreads();
            if (kt + 1 < ktiles) { issue_kv((kt + 1) * 64, (kt + 1) & 1); cp_commit(); }

            const uint32_t kvb = sb + A_KV + (uint32_t)(kt & 1) * A_KVSTG;
            const uint32_t sKH = kvb, sVH = kvb + AKTILEB;

            // ---- S = Q K^T ----
            float s_[8][4] = {};
            #pragma unroll
            for (int ks = 0; ks < 8; ks++) {
                const uint32_t koff = ks * 32;
                uint32_t aq[4];
                uint32_t ra = (uint32_t)((wid * 16) * AQROWB) + koff;
                ldsm_x4(aq, sb + A_SQ + ra + laA);
                #pragma unroll
                for (int nj2 = 0; nj2 < 4; nj2++) {
                    uint32_t rb = (uint32_t)((nj2 * 16) * AQROWB) + koff + laB;
                    uint32_t th[4];
                    ldsm_x4(th, sKH + rb);
                    mma_f16(s_[2 * nj2],     aq, th);
                    mma_f16(s_[2 * nj2 + 1], aq, th + 2);
                }
            }

            // ---- scale (log2 domain) + causal mask ----
            const int qrow0 = qbase + wid * 16 + (l >> 2);
            #pragma unroll
            for (int nj = 0; nj < 8; nj++)
                #pragma unroll
                for (int c = 0; c < 4; c++) s_[nj][c] *= SCALE_LOG2E;
            if (kbase + 63 > qbase + wid * 16) {
                #pragma unroll
                for (int nj = 0; nj < 8; nj++) {
                    int kp2 = kbase + nj * 8 + (l & 3) * 2;
                    if (kp2     > qrow0)     s_[nj][0] = -1e30f;
                    if (kp2 + 1 > qrow0)     s_[nj][1] = -1e30f;
                    if (kp2     > qrow0 + 8) s_[nj][2] = -1e30f;
                    if (kp2 + 1 > qrow0 + 8) s_[nj][3] = -1e30f;
                }
            }

            // ---- online softmax (exp2 domain) ----
            float mx0 = -1e30f, mx1 = -1e30f;
            #pragma unroll
            for (int nj = 0; nj < 8; nj++) {
                mx0 = fmaxf(mx0, fmaxf(s_[nj][0], s_[nj][1]));
                mx1 = fmaxf(mx1, fmaxf(s_[nj][2], s_[nj][3]));
            }
            mx0 = fmaxf(mx0, __shfl_xor_sync(0xffffffffu, mx0, 1));
            mx0 = fmaxf(mx0, __shfl_xor_sync(0xffffffffu, mx0, 2));
            mx1 = fmaxf(mx1, __shfl_xor_sync(0xffffffffu, mx1, 1));
            mx1 = fmaxf(mx1, __shfl_xor_sync(0xffffffffu, mx1, 2));
            float nm0 = fmaxf(rm0, mx0), nm1 = fmaxf(rm1, mx1);
            float al0 = exp2f(rm0 - nm0), al1 = exp2f(rm1 - nm1);
            rm0 = nm0; rm1 = nm1;
            float ps0 = 0.f, ps1 = 0.f;
            #pragma unroll
            for (int nj = 0; nj < 8; nj++) {
                s_[nj][0] = exp2f(s_[nj][0] - nm0);
                s_[nj][1] = exp2f(s_[nj][1] - nm0);
                s_[nj][2] = exp2f(s_[nj][2] - nm1);
                s_[nj][3] = exp2f(s_[nj][3] - nm1);
                ps0 += s_[nj][0] + s_[nj][1];
                ps1 += s_[nj][2] + s_[nj][3];
            }
            lp0 = lp0 * al0 + ps0;
            lp1 = lp1 * al1 + ps1;
            #pragma unroll
            for (int dj = 0; dj < 16; dj++) {
                o[dj][0] *= al0; o[dj][1] *= al0;
                o[dj][2] *= al1; o[dj][3] *= al1;
            }

            // ---- O += P V ----
            #pragma unroll
            for (int kks = 0; kks < 4; kks++) {
                uint32_t ap[4];
                {
                    const float* p0 = s_[2 * kks];
                    const float* p1 = s_[2 * kks + 1];
                    ap[0] = h2_as_u32(__floats2half2_rn(p0[0], p0[1]));
                    ap[1] = h2_as_u32(__floats2half2_rn(p0[2], p0[3]));
                    ap[2] = h2_as_u32(__floats2half2_rn(p1[0], p1[1]));
                    ap[3] = h2_as_u32(__floats2half2_rn(p1[2], p1[3]));
                }
                uint32_t rvb = (uint32_t)((kks * 16) * AQROWB) + laV;
                #pragma unroll
                for (int dj2 = 0; dj2 < 8; dj2++) {
                    uint32_t coff = dj2 * 32;
                    uint32_t tv[4];
                    ldsm_x4_t(tv, sVH + rvb + coff);
                    mma_f16(o[2 * dj2],     ap, tv);
                    mma_f16(o[2 * dj2 + 1], ap, tv + 2);
                }
            }
        }

        // ---- finalize this qtile ----
        lp0 += __shfl_xor_sync(0xffffffffu, lp0, 1);
        lp0 += __shfl_xor_sync(0xffffffffu, lp0, 2);
        lp1 += __shfl_xor_sync(0xffffffffu, lp1, 1);
        lp1 += __shfl_xor_sync(0xffffffffu, lp1, 2);
        float inv0 = 1.0f / lp0, inv1 = 1.0f / lp1;

        const size_t row0 = (size_t)(b * SEQ + qbase + wid * 16 + (l >> 2));
        const int colb = h * HDIM + (l & 3) * 2;
        #pragma unroll
        for (int dj = 0; dj < 16; dj++) {
            int col = colb + dj * 8;
            *(__half2*)(Yh + row0 * DMODEL + col) =
                __floats2half2_rn(o[dj][0] * inv0, o[dj][1] * inv0);
            *(__half2*)(Yh + (row0 + 8) * DMODEL + col) =
                __floats2half2_rn(o[dj][2] * inv1, o[dj][3] * inv1);
        }
    }
}

// ---------------------------------------------------------------------------
extern "C" void kernel_launch(void* const* d_in, const int* in_sizes, int n_in,
                              void* d_out, int out_size)
{
    (void)in_sizes; (void)n_in; (void)out_size;
    const float* x     = (const float*)d_in[0];
    const float* Wq    = (const float*)d_in[1];
    const float* Wkv   = (const float*)d_in[2];
    const float* Wproj = (const float*)d_in[3];
    float* out = (float*)d_out;

    __half *xh, *wh, *wph, *qkvh, *yh;
    cudaGetSymbolAddress((void**)&xh,   g_xh);
    cudaGetSymbolAddress((void**)&wh,   g_wh);
    cudaGetSymbolAddress((void**)&wph,  g_wph);
    cudaGetSymbolAddress((void**)&qkvh, g_qkvh);
    cudaGetSymbolAddress((void**)&yh,   g_yh);

    cudaFuncSetAttribute(gemm_mma<true>,  cudaFuncAttributeMaxDynamicSharedMemorySize, G_SMEM);
    cudaFuncSetAttribute(gemm_mma<false>, cudaFuncAttributeMaxDynamicSharedMemorySize, G_SMEM);
    cudaFuncSetAttribute(attn_mma, cudaFuncAttributeMaxDynamicSharedMemorySize, A_SMEM);

    // 0) input conversions (Wq|Wkv fused into one weight buffer)
    {
        int n;
        n = MTOT * DMODEL / 4;   cvt_kernel<<<n / 256, 256>>>(x,     xh,  n);
        n = DMODEL * DMODEL / 4; cvt_kernel<<<n / 256, 256>>>(Wq,    wh,  n);
        n = KVDIM * DMODEL / 4;  cvt_kernel<<<n / 256, 256>>>(Wkv,   wh + (size_t)DMODEL * DMODEL, n);
        n = DMODEL * DMODEL / 4; cvt_kernel<<<n / 256, 256>>>(Wproj, wph, n);
    }

    // 1) fused QKV = x [Wq;Wkv]^T  -> fp16 [4096, 3072]
    gemm_mma<true><<<dim3(QKVW / 128, MTOT / 128), 256, G_SMEM>>>(xh, wh, qkvh,
                                                                  MTOT, QKVW, DMODEL);

    // 2) in-place RoPE on q heads (0..15) and k heads (16..19)
    {
        int total = MTOT * (NHEAD + NKV) * (HDIM / 2);
        rope16<<<(total + 255) / 256, 256>>>(qkvh, QKVW, NHEAD + NKV);
    }

    // 3) attention -> yh (fp16), balanced qtile pairs
    attn_mma<<<dim3(SEQ / 256, BATCH * NHEAD), 256, A_SMEM>>>(qkvh, yh);

    // 4) out = y Wproj^T (fp32)
    gemm_mma<false><<<dim3(DMODEL / 128, MTOT / 128), 256, G_SMEM>>>(yh, wph, out,
                                                                     MTOT, DMODEL, DMODEL);
}

// round 8
// speedup vs baseline: 8.1260x; 1.0123x over previous
#include <cuda_runtime.h>
#include <cuda_fp16.h>
#include <cstdint>
#include <math.h>

#define BATCH  2
#define SEQ    2048
#define DMODEL 2048
#define NHEAD  16
#define NKV    4
#define HDIM   128
#define KVDIM  1024
#define QKVW   3072            // fused q|k|v row width
#define MTOT   4096

#define SCALE_LOG2E 0.12751589542466683f   // (1/sqrt(128)) * log2(e)

// ---------------- scratch ----------------
__device__ __half g_xh  [(size_t)MTOT * DMODEL];
__device__ __half g_wh  [(size_t)QKVW * DMODEL];     // [Wq; Wkv] fp16
__device__ __half g_wph [(size_t)DMODEL * DMODEL];
__device__ __half g_qkvh[(size_t)MTOT * QKVW];       // fused q|k|v fp16
__device__ __half g_yh  [(size_t)MTOT * DMODEL];

// ---------------- helpers ----------------
__device__ __forceinline__ uint32_t smem_u32(const void* p) {
    uint32_t a;
    asm("{ .reg .u64 t; cvta.to.shared.u64 t, %1; cvt.u32.u64 %0, t; }" : "=r"(a) : "l"(p));
    return a;
}
__device__ __forceinline__ void ldsm_x4(uint32_t* r, uint32_t addr) {
    asm volatile("ldmatrix.sync.aligned.m8n8.x4.shared.b16 {%0,%1,%2,%3}, [%4];"
                 : "=r"(r[0]), "=r"(r[1]), "=r"(r[2]), "=r"(r[3]) : "r"(addr));
}
__device__ __forceinline__ void ldsm_x4_t(uint32_t* r, uint32_t addr) {
    asm volatile("ldmatrix.sync.aligned.m8n8.x4.trans.shared.b16 {%0,%1,%2,%3}, [%4];"
                 : "=r"(r[0]), "=r"(r[1]), "=r"(r[2]), "=r"(r[3]) : "r"(addr));
}
__device__ __forceinline__ void mma_f16(float* d, const uint32_t* a, const uint32_t* b) {
    asm volatile(
        "mma.sync.aligned.m16n8k16.row.col.f32.f16.f16.f32 "
        "{%0,%1,%2,%3}, {%4,%5,%6,%7}, {%8,%9}, {%0,%1,%2,%3};"
        : "+f"(d[0]), "+f"(d[1]), "+f"(d[2]), "+f"(d[3])
        : "r"(a[0]), "r"(a[1]), "r"(a[2]), "r"(a[3]), "r"(b[0]), "r"(b[1]));
}
__device__ __forceinline__ uint32_t h2_as_u32(__half2 v) {
    return *reinterpret_cast<uint32_t*>(&v);
}
__device__ __forceinline__ void cp_async16(uint32_t dst, const void* src) {
    asm volatile("cp.async.cg.shared.global [%0], [%1], 16;" :: "r"(dst), "l"(src));
}
__device__ __forceinline__ void cp_commit() {
    asm volatile("cp.async.commit_group;" ::: "memory");
}
template <int N>
__device__ __forceinline__ void cp_wait() {
    asm volatile("cp.async.wait_group %0;" :: "n"(N) : "memory");
}

// ---------------- single fused fp32 -> fp16 conversion pass ----------------
#define CVT_N1 (MTOT * DMODEL / 4)          // x
#define CVT_N2 (DMODEL * DMODEL / 4)        // Wq
#define CVT_N3 (KVDIM * DMODEL / 4)         // Wkv
#define CVT_N4 (DMODEL * DMODEL / 4)        // Wproj
#define CVT_TOTAL (CVT_N1 + CVT_N2 + CVT_N3 + CVT_N4)

__global__ void cvt_all(const float* __restrict__ x,   const float* __restrict__ wq,
                        const float* __restrict__ wkv, const float* __restrict__ wp,
                        __half* __restrict__ xh, __half* __restrict__ wh,
                        __half* __restrict__ wph)
{
    int i = blockIdx.x * blockDim.x + threadIdx.x;
    if (i >= CVT_TOTAL) return;
    const float* src;
    __half* dst;
    int j;
    if (i < CVT_N1)                       { src = x;   dst = xh;  j = i; }
    else if (i < CVT_N1 + CVT_N2)         { src = wq;  dst = wh;  j = i - CVT_N1; }
    else if (i < CVT_N1 + CVT_N2 + CVT_N3){ src = wkv; dst = wh + (size_t)DMODEL * DMODEL;
                                            j = i - CVT_N1 - CVT_N2; }
    else                                  { src = wp;  dst = wph; j = i - CVT_N1 - CVT_N2 - CVT_N3; }
    float4 v = ((const float4*)src)[j];
    union { __half b[4]; uint2 u; } H;
    H.b[0] = __float2half_rn(v.x); H.b[1] = __float2half_rn(v.y);
    H.b[2] = __float2half_rn(v.z); H.b[3] = __float2half_rn(v.w);
    ((uint2*)dst)[j] = H.u;
}

// ---------------- in-place fp16 RoPE; k heads (>=NHEAD) also get scale folded --
__global__ void rope16(__half* __restrict__ buf, int rowstride, int nheads)
{
    int idx = blockIdx.x * blockDim.x + threadIdx.x;
    int total = MTOT * nheads * (HDIM / 2);
    if (idx >= total) return;
    int j = idx & 63;
    int h = (idx >> 6) % nheads;
    int m = idx / (64 * nheads);
    int t = m & (SEQ - 1);
    float freq = powf(10000.0f, (float)j * (1.0f / 64.0f));
    float ang  = (float)t / freq;
    float s, c;
    sincosf(ang, &s, &c);
    float post = (h >= NHEAD) ? SCALE_LOG2E : 1.0f;   // fold softmax scale into K
    size_t o = (size_t)m * rowstride + h * HDIM;
    float x1 = __half2float(buf[o + j]);
    float x2 = __half2float(buf[o + j + 64]);
    buf[o + j]      = __float2half_rn((x1 * c - x2 * s) * post);
    buf[o + j + 64] = __float2half_rn((x2 * c + x1 * s) * post);
}

// ---------------------------------------------------------------------------
// HMMA fp16 NT GEMM: C = A B^T. fp32 accum; output fp16 or fp32 (template).
// CTA 128x128, BK=32, 8 warps (4m x 2n), cp.async 3-stage, 2 CTA/SM.
// ---------------------------------------------------------------------------
#define GBK     32
#define G_ROWB  80
#define G_TILEB (128 * G_ROWB)     // 10240
#define G_STGB  (2 * G_TILEB)      // 20480
#define G_SMEM  (3 * G_STGB)       // 61440

template <bool HALF_OUT>
__global__ __launch_bounds__(256, 2)
void gemm_mma(const __half* __restrict__ A, const __half* __restrict__ B,
              void* __restrict__ Cv, int M, int N, int K)
{
    extern __shared__ char smem[];
    const uint32_t sb0 = smem_u32(smem);
    const int tid = threadIdx.x, l = tid & 31, wid = tid >> 5;
    const int wm = wid & 3, wn = wid >> 2;
    const int mbase = blockIdx.y * 128, nbase = blockIdx.x * 128;

    const int g_row0 = tid >> 2, g_c = tid & 3;
    const int g_row1 = g_row0 + 64;

    const uint32_t laA = (uint32_t)((l & 15) * G_ROWB + (l >> 4) * 16);
    const uint32_t laB = (uint32_t)(((((l >> 4) << 3) | (l & 7)) * G_ROWB) + (((l >> 3) & 1) * 16));

    float acc[2][8][4] = {};

    auto issue = [&](int kb, int stg) {
        const uint32_t sb = sb0 + (uint32_t)stg * G_STGB;
        const uint32_t o0 = (uint32_t)(g_row0 * G_ROWB + g_c * 16);
        const uint32_t o1 = (uint32_t)(g_row1 * G_ROWB + g_c * 16);
        size_t a0 = (size_t)(mbase + g_row0) * K + kb + g_c * 8;
        size_t a1 = (size_t)(mbase + g_row1) * K + kb + g_c * 8;
        size_t b0 = (size_t)(nbase + g_row0) * K + kb + g_c * 8;
        size_t b1 = (size_t)(nbase + g_row1) * K + kb + g_c * 8;
        cp_async16(sb + 0 * G_TILEB + o0, A + a0);
        cp_async16(sb + 0 * G_TILEB + o1, A + a1);
        cp_async16(sb + 1 * G_TILEB + o0, B + b0);
        cp_async16(sb + 1 * G_TILEB + o1, B + b1);
    };

    const int NC = K / GBK;
    issue(0, 0); cp_commit();
    issue(GBK, 1); cp_commit();

    int stg = 0;
    for (int i = 0; i < NC; i++) {
        cp_wait<1>();
        __syncthreads();
        {
            int s2 = stg + 2; if (s2 >= 3) s2 -= 3;
            if (i + 2 < NC) issue((i + 2) * GBK, s2);
            cp_commit();
        }

        const uint32_t base = sb0 + (uint32_t)stg * G_STGB;
        const uint32_t sA = base, sB = base + G_TILEB;
        #pragma unroll
        for (int ks = 0; ks < 2; ks++) {
            const uint32_t koff = ks * 32;
            uint32_t af[2][4];
            #pragma unroll
            for (int mi = 0; mi < 2; mi++) {
                uint32_t ra = (uint32_t)((wm * 32 + mi * 16) * G_ROWB) + koff + laA;
                ldsm_x4(af[mi], sA + ra);
            }
            #pragma unroll
            for (int nj2 = 0; nj2 < 4; nj2++) {
                uint32_t rb = (uint32_t)(((wn * 64) + nj2 * 16) * G_ROWB) + koff + laB;
                uint32_t bf[4];
                ldsm_x4(bf, sB + rb);
                #pragma unroll
                for (int mi = 0; mi < 2; mi++) {
                    mma_f16(acc[mi][2 * nj2],     af[mi], bf);
                    mma_f16(acc[mi][2 * nj2 + 1], af[mi], bf + 2);
                }
            }
        }
        if (++stg == 3) stg = 0;
    }

    #pragma unroll
    for (int mi = 0; mi < 2; mi++) {
        int row = mbase + wm * 32 + mi * 16 + (l >> 2);
        #pragma unroll
        for (int nj = 0; nj < 8; nj++) {
            int col = nbase + wn * 64 + nj * 8 + (l & 3) * 2;
            if (HALF_OUT) {
                __half* C = (__half*)Cv;
                *(__half2*)&C[(size_t)row * N + col] =
                    __floats2half2_rn(acc[mi][nj][0], acc[mi][nj][1]);
                *(__half2*)&C[(size_t)(row + 8) * N + col] =
                    __floats2half2_rn(acc[mi][nj][2], acc[mi][nj][3]);
            } else {
                float* C = (float*)Cv;
                *(float2*)&C[(size_t)row * N + col] =
                    make_float2(acc[mi][nj][0], acc[mi][nj][1]);
                *(float2*)&C[(size_t)(row + 8) * N + col] =
                    make_float2(acc[mi][nj][2], acc[mi][nj][3]);
            }
        }
    }
}

// ---------------------------------------------------------------------------
// HMMA fp16 flash attention, causal, GQA; fused QKV input (row stride 3072).
// K pre-scaled by scale*log2e -> S already in log2 domain.
// Grid (8, 32): each CTA does qtile pair (i, 15-i): balanced single wave.
// ---------------------------------------------------------------------------
#define AQROWB  272
#define AQTILEB (128 * AQROWB)       // 34816
#define AKTILEB (64 * AQROWB)        // 17408
#define A_SQ    0
#define A_KV    (A_SQ + AQTILEB)
#define A_KVSTG (2 * AKTILEB)
#define A_SMEM  (A_KV + 2 * A_KVSTG) // 104448

__global__ __launch_bounds__(256, 2)
void attn_mma(const __half* __restrict__ QKV, __half* __restrict__ Yh)
{
    extern __shared__ char smem[];
    const uint32_t sb = smem_u32(smem);
    const int tid = threadIdx.x, l = tid & 31, wid = tid >> 5;
    const int bhidx = blockIdx.y;
    const int b = bhidx >> 4, h = bhidx & 15, kvh = h >> 2;

    const __half* kp = QKV + (size_t)(b * SEQ) * QKVW + DMODEL + kvh * HDIM;

    auto issue_kv = [&](int kbase, int stg) {
        const uint32_t sbase = sb + A_KV + (uint32_t)stg * A_KVSTG;
        #pragma unroll
        for (int j = 0; j < 4; j++) {
            int s = tid + j * 256;
            int row = s >> 4, c = s & 15;
            size_t src = (size_t)(kbase + row) * QKVW + c * 8;
            uint32_t dst = (uint32_t)(row * AQROWB + c * 16);
            cp_async16(sbase + 0 * AKTILEB + dst, kp + src);          // K
            cp_async16(sbase + 1 * AKTILEB + dst, kp + src + 512);    // V
        }
    };

    const uint32_t laA = (uint32_t)((l & 15) * AQROWB + (l >> 4) * 16);
    const uint32_t laB = (uint32_t)(((((l >> 4) << 3) | (l & 7)) * AQROWB) + (((l >> 3) & 1) * 16));
    const uint32_t laV = (uint32_t)(((((l >> 3) & 1) * 8 + (l & 7)) * AQROWB) + ((l >> 4) * 16));

    #pragma unroll 1
    for (int pass = 0; pass < 2; pass++) {
        const int qtile = pass == 0 ? (int)blockIdx.x : (int)(15 - blockIdx.x);
        const int qbase = qtile * 128;

        __syncthreads();   // previous pass finished all smem reads

        // Q tile load
        {
            const __half* qh = QKV + ((size_t)(b * SEQ + qbase)) * QKVW + h * HDIM;
            #pragma unroll
            for (int j = 0; j < 8; j++) {
                int s = tid + j * 256;
                int row = s >> 4, c = s & 15;
                size_t src = (size_t)row * QKVW + c * 8;
                uint32_t dst = (uint32_t)(row * AQROWB + c * 16);
                *(uint4*)(smem + A_SQ + dst) = *(const uint4*)(qh + src);
            }
        }

        issue_kv(0, 0);
        cp_commit();

        float o[16][4] = {};
        float rm0 = -1e30f, rm1 = -1e30f, lp0 = 0.f, lp1 = 0.f;
        const int ktiles = 2 * qtile + 2;

        for (int kt = 0; kt < ktiles; kt++) {
            const int kbase = kt * 64;
            cp_wait<0>();
            __syncthreads();
            if (kt + 1 < ktiles) { issue_kv((kt + 1) * 64, (kt + 1) & 1); cp_commit(); }

            const uint32_t kvb = sb + A_KV + (uint32_t)(kt & 1) * A_KVSTG;
            const uint32_t sKH = kvb, sVH = kvb + AKTILEB;

            // ---- S = Q K^T (already in log2 domain; K pre-scaled) ----
            float s_[8][4] = {};
            #pragma unroll
            for (int ks = 0; ks < 8; ks++) {
                const uint32_t koff = ks * 32;
                uint32_t aq[4];
                uint32_t ra = (uint32_t)((wid * 16) * AQROWB) + koff;
                ldsm_x4(aq, sb + A_SQ + ra + laA);
                #pragma unroll
                for (int nj2 = 0; nj2 < 4; nj2++) {
                    uint32_t rb = (uint32_t)((nj2 * 16) * AQROWB) + koff + laB;
                    uint32_t th[4];
                    ldsm_x4(th, sKH + rb);
                    mma_f16(s_[2 * nj2],     aq, th);
                    mma_f16(s_[2 * nj2 + 1], aq, th + 2);
                }
            }

            // ---- causal mask ----
            const int qrow0 = qbase + wid * 16 + (l >> 2);
            if (kbase + 63 > qbase + wid * 16) {
                #pragma unroll
                for (int nj = 0; nj < 8; nj++) {
                    int kp2 = kbase + nj * 8 + (l & 3) * 2;
                    if (kp2     > qrow0)     s_[nj][0] = -1e30f;
                    if (kp2 + 1 > qrow0)     s_[nj][1] = -1e30f;
                    if (kp2     > qrow0 + 8) s_[nj][2] = -1e30f;
                    if (kp2 + 1 > qrow0 + 8) s_[nj][3] = -1e30f;
                }
            }

            // ---- online softmax (exp2 domain) ----
            float mx0 = -1e30f, mx1 = -1e30f;
            #pragma unroll
            for (int nj = 0; nj < 8; nj++) {
                mx0 = fmaxf(mx0, fmaxf(s_[nj][0], s_[nj][1]));
                mx1 = fmaxf(mx1, fmaxf(s_[nj][2], s_[nj][3]));
            }
            mx0 = fmaxf(mx0, __shfl_xor_sync(0xffffffffu, mx0, 1));
            mx0 = fmaxf(mx0, __shfl_xor_sync(0xffffffffu, mx0, 2));
            mx1 = fmaxf(mx1, __shfl_xor_sync(0xffffffffu, mx1, 1));
            mx1 = fmaxf(mx1, __shfl_xor_sync(0xffffffffu, mx1, 2));
            float nm0 = fmaxf(rm0, mx0), nm1 = fmaxf(rm1, mx1);

            // warp-uniform rescale skip: alpha==1 exactly when max unchanged
            bool changed = (nm0 != rm0) | (nm1 != rm1);
            if (__any_sync(0xffffffffu, changed)) {
                float al0 = exp2f(rm0 - nm0), al1 = exp2f(rm1 - nm1);
                lp0 *= al0; lp1 *= al1;
                #pragma unroll
                for (int dj = 0; dj < 16; dj++) {
                    o[dj][0] *= al0; o[dj][1] *= al0;
                    o[dj][2] *= al1; o[dj][3] *= al1;
                }
                rm0 = nm0; rm1 = nm1;
            }

            float ps0 = 0.f, ps1 = 0.f;
            #pragma unroll
            for (int nj = 0; nj < 8; nj++) {
                s_[nj][0] = exp2f(s_[nj][0] - rm0);
                s_[nj][1] = exp2f(s_[nj][1] - rm0);
                s_[nj][2] = exp2f(s_[nj][2] - rm1);
                s_[nj][3] = exp2f(s_[nj][3] - rm1);
                ps0 += s_[nj][0] + s_[nj][1];
                ps1 += s_[nj][2] + s_[nj][3];
            }
            lp0 += ps0;
            lp1 += ps1;

            // ---- O += P V ----
            #pragma unroll
            for (int kks = 0; kks < 4; kks++) {
                uint32_t ap[4];
                {
                    const float* p0 = s_[2 * kks];
                    const float* p1 = s_[2 * kks + 1];
                    ap[0] = h2_as_u32(__floats2half2_rn(p0[0], p0[1]));
                    ap[1] = h2_as_u32(__floats2half2_rn(p0[2], p0[3]));
                    ap[2] = h2_as_u32(__floats2half2_rn(p1[0], p1[1]));
                    ap[3] = h2_as_u32(__floats2half2_rn(p1[2], p1[3]));
                }
                uint32_t rvb = (uint32_t)((kks * 16) * AQROWB) + laV;
                #pragma unroll
                for (int dj2 = 0; dj2 < 8; dj2++) {
                    uint32_t coff = dj2 * 32;
                    uint32_t tv[4];
                    ldsm_x4_t(tv, sVH + rvb + coff);
                    mma_f16(o[2 * dj2],     ap, tv);
                    mma_f16(o[2 * dj2 + 1], ap, tv + 2);
                }
            }
        }

        // ---- finalize this qtile ----
        lp0 += __shfl_xor_sync(0xffffffffu, lp0, 1);
        lp0 += __shfl_xor_sync(0xffffffffu, lp0, 2);
        lp1 += __shfl_xor_sync(0xffffffffu, lp1, 1);
        lp1 += __shfl_xor_sync(0xffffffffu, lp1, 2);
        float inv0 = 1.0f / lp0, inv1 = 1.0f / lp1;

        const size_t row0 = (size_t)(b * SEQ + qbase + wid * 16 + (l >> 2));
        const int colb = h * HDIM + (l & 3) * 2;
        #pragma unroll
        for (int dj = 0; dj < 16; dj++) {
            int col = colb + dj * 8;
            *(__half2*)(Yh + row0 * DMODEL + col) =
                __floats2half2_rn(o[dj][0] * inv0, o[dj][1] * inv0);
            *(__half2*)(Yh + (row0 + 8) * DMODEL + col) =
                __floats2half2_rn(o[dj][2] * inv1, o[dj][3] * inv1);
        }
    }
}

// ---------------------------------------------------------------------------
extern "C" void kernel_launch(void* const* d_in, const int* in_sizes, int n_in,
                              void* d_out, int out_size)
{
    (void)in_sizes; (void)n_in; (void)out_size;
    const float* x     = (const float*)d_in[0];
    const float* Wq    = (const float*)d_in[1];
    const float* Wkv   = (const float*)d_in[2];
    const float* Wproj = (const float*)d_in[3];
    float* out = (float*)d_out;

    __half *xh, *wh, *wph, *qkvh, *yh;
    cudaGetSymbolAddress((void**)&xh,   g_xh);
    cudaGetSymbolAddress((void**)&wh,   g_wh);
    cudaGetSymbolAddress((void**)&wph,  g_wph);
    cudaGetSymbolAddress((void**)&qkvh, g_qkvh);
    cudaGetSymbolAddress((void**)&yh,   g_yh);

    cudaFuncSetAttribute(gemm_mma<true>,  cudaFuncAttributeMaxDynamicSharedMemorySize, G_SMEM);
    cudaFuncSetAttribute(gemm_mma<false>, cudaFuncAttributeMaxDynamicSharedMemorySize, G_SMEM);
    cudaFuncSetAttribute(attn_mma, cudaFuncAttributeMaxDynamicSharedMemorySize, A_SMEM);

    // 0) all fp32->fp16 conversions in one launch
    cvt_all<<<(CVT_TOTAL + 255) / 256, 256>>>(x, Wq, Wkv, Wproj, xh, wh, wph);

    // 1) fused QKV = x [Wq;Wkv]^T  -> fp16 [4096, 3072]
    gemm_mma<true><<<dim3(QKVW / 128, MTOT / 128), 256, G_SMEM>>>(xh, wh, qkvh,
                                                                  MTOT, QKVW, DMODEL);

    // 2) in-place RoPE on q heads (0..15) and k heads (16..19, scale folded)
    {
        int total = MTOT * (NHEAD + NKV) * (HDIM / 2);
        rope16<<<(total + 255) / 256, 256>>>(qkvh, QKVW, NHEAD + NKV);
    }

    // 3) attention -> yh (fp16), balanced qtile pairs
    attn_mma<<<dim3(SEQ / 256, BATCH * NHEAD), 256, A_SMEM>>>(qkvh, yh);

    // 4) out = y Wproj^T (fp32)
    gemm_mma<false><<<dim3(DMODEL / 128, MTOT / 128), 256, G_SMEM>>>(yh, wph, out,
                                                                     MTOT, DMODEL, DMODEL);
}

// round 10
// speedup vs baseline: 8.4154x; 1.0356x over previous
#include <cuda_runtime.h>
#include <cuda_fp16.h>
#include <cstdint>
#include <math.h>

#define BATCH  2
#define SEQ    2048
#define DMODEL 2048
#define NHEAD  16
#define NKV    4
#define HDIM   128
#define KVDIM  1024
#define QKVW   3072            // fused q|k|v row width
#define MTOT   4096

#define SCALE_LOG2E 0.12751589542466683f   // (1/sqrt(128)) * log2(e)

// ---------------- scratch ----------------
__device__ __half g_xh  [(size_t)MTOT * DMODEL];
__device__ __half g_wh  [(size_t)QKVW * DMODEL];     // [Wq; Wkv] fp16
__device__ __half g_wph [(size_t)DMODEL * DMODEL];
__device__ __half g_qkvh[(size_t)MTOT * QKVW];       // fused q|k|v fp16
__device__ __half g_yh  [(size_t)MTOT * DMODEL];

// ---------------- helpers ----------------
__device__ __forceinline__ uint32_t smem_u32(const void* p) {
    uint32_t a;
    asm("{ .reg .u64 t; cvta.to.shared.u64 t, %1; cvt.u32.u64 %0, t; }" : "=r"(a) : "l"(p));
    return a;
}
__device__ __forceinline__ void ldsm_x4(uint32_t* r, uint32_t addr) {
    asm volatile("ldmatrix.sync.aligned.m8n8.x4.shared.b16 {%0,%1,%2,%3}, [%4];"
                 : "=r"(r[0]), "=r"(r[1]), "=r"(r[2]), "=r"(r[3]) : "r"(addr));
}
__device__ __forceinline__ void ldsm_x4_t(uint32_t* r, uint32_t addr) {
    asm volatile("ldmatrix.sync.aligned.m8n8.x4.trans.shared.b16 {%0,%1,%2,%3}, [%4];"
                 : "=r"(r[0]), "=r"(r[1]), "=r"(r[2]), "=r"(r[3]) : "r"(addr));
}
__device__ __forceinline__ void mma_f16(float* d, const uint32_t* a, const uint32_t* b) {
    asm volatile(
        "mma.sync.aligned.m16n8k16.row.col.f32.f16.f16.f32 "
        "{%0,%1,%2,%3}, {%4,%5,%6,%7}, {%8,%9}, {%0,%1,%2,%3};"
        : "+f"(d[0]), "+f"(d[1]), "+f"(d[2]), "+f"(d[3])
        : "r"(a[0]), "r"(a[1]), "r"(a[2]), "r"(a[3]), "r"(b[0]), "r"(b[1]));
}
__device__ __forceinline__ uint32_t h2_as_u32(__half2 v) {
    return *reinterpret_cast<uint32_t*>(&v);
}
__device__ __forceinline__ void cp_async16(uint32_t dst, const void* src) {
    asm volatile("cp.async.cg.shared.global [%0], [%1], 16;" :: "r"(dst), "l"(src));
}
__device__ __forceinline__ void cp_commit() {
    asm volatile("cp.async.commit_group;" ::: "memory");
}
template <int N>
__device__ __forceinline__ void cp_wait() {
    asm volatile("cp.async.wait_group %0;" :: "n"(N) : "memory");
}

// ---------------- single fused fp32 -> fp16 conversion pass (MLP=4) --------
#define CVT_N1 (MTOT * DMODEL / 4)          // x
#define CVT_N2 (DMODEL * DMODEL / 4)        // Wq
#define CVT_N3 (KVDIM * DMODEL / 4)         // Wkv
#define CVT_N4 (DMODEL * DMODEL / 4)        // Wproj
#define CVT_TOTAL (CVT_N1 + CVT_N2 + CVT_N3 + CVT_N4)

__global__ void cvt_all(const float* __restrict__ x,   const float* __restrict__ wq,
                        const float* __restrict__ wkv, const float* __restrict__ wp,
                        __half* __restrict__ xh, __half* __restrict__ wh,
                        __half* __restrict__ wph)
{
    int stride = gridDim.x * blockDim.x;
    int i0 = blockIdx.x * blockDim.x + threadIdx.x;
    #pragma unroll
    for (int u = 0; u < 4; u++) {
        int i = i0 + u * stride;
        if (i >= CVT_TOTAL) return;
        const float* src;
        __half* dst;
        int j;
        if (i < CVT_N1)                        { src = x;   dst = xh;  j = i; }
        else if (i < CVT_N1 + CVT_N2)          { src = wq;  dst = wh;  j = i - CVT_N1; }
        else if (i < CVT_N1 + CVT_N2 + CVT_N3) { src = wkv; dst = wh + (size_t)DMODEL * DMODEL;
                                                 j = i - CVT_N1 - CVT_N2; }
        else                                   { src = wp;  dst = wph; j = i - CVT_N1 - CVT_N2 - CVT_N3; }
        float4 v = ((const float4*)src)[j];
        union { __half b[4]; uint2 u2; } H;
        H.b[0] = __float2half_rn(v.x); H.b[1] = __float2half_rn(v.y);
        H.b[2] = __float2half_rn(v.z); H.b[3] = __float2half_rn(v.w);
        ((uint2*)dst)[j] = H.u2;
    }
}

// ---------------- in-place fp16 RoPE; k heads (>=NHEAD) get scale folded ----
// log2(10000)/64 — CORRECTED constant (R9 had 0.207759..., off by 6.7e-4)
#define LOG2_10000_OVER64 0.20762050593046938f

__global__ void rope16(__half* __restrict__ buf, int rowstride, int nheads)
{
    int idx = blockIdx.x * blockDim.x + threadIdx.x;
    int total = MTOT * nheads * (HDIM / 2);
    if (idx >= total) return;
    int j = idx & 63;
    int h = (idx >> 6) % nheads;
    int m = idx / (64 * nheads);
    int t = m & (SEQ - 1);
    float inv_freq = exp2f(-(float)j * LOG2_10000_OVER64);
    float ang = (float)t * inv_freq;
    float s, c;
    sincosf(ang, &s, &c);
    float post = (h >= NHEAD) ? SCALE_LOG2E : 1.0f;
    size_t o = (size_t)m * rowstride + h * HDIM;
    float x1 = __half2float(buf[o + j]);
    float x2 = __half2float(buf[o + j + 64]);
    buf[o + j]      = __float2half_rn((x1 * c - x2 * s) * post);
    buf[o + j + 64] = __float2half_rn((x2 * c + x1 * s) * post);
}

// ---------------------------------------------------------------------------
// HMMA fp16 NT GEMM: C = A B^T. fp32 accum; output fp16 or fp32 (template).
// CTA 128x128, BK=64, 8 warps (4m x 2n), cp.async 3-stage, 2 CTA/SM.
// Row pitch 144B (128 data + 16 pad).
// ---------------------------------------------------------------------------
#define GBK     64
#define G_ROWB  144
#define G_TILEB (128 * G_ROWB)     // 18432
#define G_STGB  (2 * G_TILEB)      // 36864
#define G_SMEM  (3 * G_STGB)       // 110592

template <bool HALF_OUT>
__global__ __launch_bounds__(256, 2)
void gemm_mma(const __half* __restrict__ A, const __half* __restrict__ B,
              void* __restrict__ Cv, int M, int N, int K)
{
    extern __shared__ char smem[];
    const uint32_t sb0 = smem_u32(smem);
    const int tid = threadIdx.x, l = tid & 31, wid = tid >> 5;
    const int wm = wid & 3, wn = wid >> 2;
    const int mbase = blockIdx.y * 128, nbase = blockIdx.x * 128;

    const int g_row = tid >> 3;          // 0..31
    const int g_c   = tid & 7;           // 16B chunk within 128B row

    const uint32_t laA = (uint32_t)((l & 15) * G_ROWB + (l >> 4) * 16);
    const uint32_t laB = (uint32_t)(((((l >> 4) << 3) | (l & 7)) * G_ROWB) + (((l >> 3) & 1) * 16));

    float acc[2][8][4] = {};

    auto issue = [&](int kb, int stg) {
        const uint32_t sb = sb0 + (uint32_t)stg * G_STGB;
        #pragma unroll
        for (int j = 0; j < 4; j++) {
            int row = g_row + j * 32;
            uint32_t dst = (uint32_t)(row * G_ROWB + g_c * 16);
            size_t sa  = (size_t)(mbase + row) * K + kb + g_c * 8;
            size_t sbg = (size_t)(nbase + row) * K + kb + g_c * 8;
            cp_async16(sb + dst, A + sa);
            cp_async16(sb + G_TILEB + dst, B + sbg);
        }
    };

    const int NC = K / GBK;
    issue(0, 0); cp_commit();
    issue(GBK, 1); cp_commit();

    int stg = 0;
    for (int i = 0; i < NC; i++) {
        cp_wait<1>();
        __syncthreads();
        {
            int s2 = stg + 2; if (s2 >= 3) s2 -= 3;
            if (i + 2 < NC) issue((i + 2) * GBK, s2);
            cp_commit();
        }

        const uint32_t base = sb0 + (uint32_t)stg * G_STGB;
        const uint32_t sA = base, sB = base + G_TILEB;
        #pragma unroll
        for (int ks = 0; ks < 4; ks++) {
            const uint32_t koff = ks * 32;
            uint32_t af[2][4];
            #pragma unroll
            for (int mi = 0; mi < 2; mi++) {
                uint32_t ra = (uint32_t)((wm * 32 + mi * 16) * G_ROWB) + koff + laA;
                ldsm_x4(af[mi], sA + ra);
            }
            #pragma unroll
            for (int nj2 = 0; nj2 < 4; nj2++) {
                uint32_t rb = (uint32_t)(((wn * 64) + nj2 * 16) * G_ROWB) + koff + laB;
                uint32_t bf[4];
                ldsm_x4(bf, sB + rb);
                #pragma unroll
                for (int mi = 0; mi < 2; mi++) {
                    mma_f16(acc[mi][2 * nj2],     af[mi], bf);
                    mma_f16(acc[mi][2 * nj2 + 1], af[mi], bf + 2);
                }
            }
        }
        if (++stg == 3) stg = 0;
    }

    #pragma unroll
    for (int mi = 0; mi < 2; mi++) {
        int row = mbase + wm * 32 + mi * 16 + (l >> 2);
        #pragma unroll
        for (int nj = 0; nj < 8; nj++) {
            int col = nbase + wn * 64 + nj * 8 + (l & 3) * 2;
            if (HALF_OUT) {
                __half* C = (__half*)Cv;
                *(__half2*)&C[(size_t)row * N + col] =
                    __floats2half2_rn(acc[mi][nj][0], acc[mi][nj][1]);
                *(__half2*)&C[(size_t)(row + 8) * N + col] =
                    __floats2half2_rn(acc[mi][nj][2], acc[mi][nj][3]);
            } else {
                float* C = (float*)Cv;
                *(float2*)&C[(size_t)row * N + col] =
                    make_float2(acc[mi][nj][0], acc[mi][nj][1]);
                *(float2*)&C[(size_t)(row + 8) * N + col] =
                    make_float2(acc[mi][nj][2], acc[mi][nj][3]);
            }
        }
    }
}

// ---------------------------------------------------------------------------
// HMMA fp16 flash attention, causal, GQA; fused QKV input (row stride 3072).
// K pre-scaled by scale*log2e -> S already in log2 domain.
// Grid (8, 32): each CTA does qtile pair (i, 15-i): balanced single wave.
// ---------------------------------------------------------------------------
#define AQROWB  272
#define AQTILEB (128 * AQROWB)       // 34816
#define AKTILEB (64 * AQROWB)        // 17408
#define A_SQ    0
#define A_KV    (A_SQ + AQTILEB)
#define A_KVSTG (2 * AKTILEB)
#define A_SMEM  (A_KV + 2 * A_KVSTG) // 104448

__global__ __launch_bounds__(256, 2)
void attn_mma(const __half* __restrict__ QKV, __half* __restrict__ Yh)
{
    extern __shared__ char smem[];
    const uint32_t sb = smem_u32(smem);
    const int tid = threadIdx.x, l = tid & 31, wid = tid >> 5;
    const int bhidx = blockIdx.y;
    const int b = bhidx >> 4, h = bhidx & 15, kvh = h >> 2;

    const __half* kp = QKV + (size_t)(b * SEQ) * QKVW + DMODEL + kvh * HDIM;

    auto issue_kv = [&](int kbase, int stg) {
        const uint32_t sbase = sb + A_KV + (uint32_t)stg * A_KVSTG;
        #pragma unroll
        for (int j = 0; j < 4; j++) {
            int s = tid + j * 256;
            int row = s >> 4, c = s & 15;
            size_t src = (size_t)(kbase + row) * QKVW + c * 8;
            uint32_t dst = (uint32_t)(row * AQROWB + c * 16);
            cp_async16(sbase + 0 * AKTILEB + dst, kp + src);          // K
            cp_async16(sbase + 1 * AKTILEB + dst, kp + src + 512);    // V
        }
    };

    const uint32_t laA = (uint32_t)((l & 15) * AQROWB + (l >> 4) * 16);
    const uint32_t laB = (uint32_t)(((((l >> 4) << 3) | (l & 7)) * AQROWB) + (((l >> 3) & 1) * 16));
    const uint32_t laV = (uint32_t)(((((l >> 3) & 1) * 8 + (l & 7)) * AQROWB) + ((l >> 4) * 16));

    #pragma unroll 1
    for (int pass = 0; pass < 2; pass++) {
        const int qtile = pass == 0 ? (int)blockIdx.x : (int)(15 - blockIdx.x);
        const int qbase = qtile * 128;

        __syncthreads();   // previous pass finished all smem reads

        // Q tile load
        {
            const __half* qh = QKV + ((size_t)(b * SEQ + qbase)) * QKVW + h * HDIM;
            #pragma unroll
            for (int j = 0; j < 8; j++) {
                int s = tid + j * 256;
                int row = s >> 4, c = s & 15;
                size_t src = (size_t)row * QKVW + c * 8;
                uint32_t dst = (uint32_t)(row * AQROWB + c * 16);
                *(uint4*)(smem + A_SQ + dst) = *(const uint4*)(qh + src);
            }
        }

        issue_kv(0, 0);
        cp_commit();

        float o[16][4] = {};
        float rm0 = -1e30f, rm1 = -1e30f, lp0 = 0.f, lp1 = 0.f;
        const int ktiles = 2 * qtile + 2;

        for (int kt = 0; kt < ktiles; kt++) {
            const int kbase = kt * 64;
            cp_wait<0>();
            __syncthreads();
            if (kt + 1 < ktiles) { issue_kv((kt + 1) * 64, (kt + 1) & 1); cp_commit(); }

            const uint32_t kvb = sb + A_KV + (uint32_t)(kt & 1) * A_KVSTG;
            const uint32_t sKH = kvb, sVH = kvb + AKTILEB;

            // ---- S = Q K^T (log2 domain; K pre-scaled) ----
            float s_[8][4] = {};
            #pragma unroll
            for (int ks = 0; ks < 8; ks++) {
                const uint32_t koff = ks * 32;
                uint32_t aq[4];
                uint32_t ra = (uint32_t)((wid * 16) * AQROWB) + koff;
                ldsm_x4(aq, sb + A_SQ + ra + laA);
                #pragma unroll
                for (int nj2 = 0; nj2 < 4; nj2++) {
                    uint32_t rb = (uint32_t)((nj2 * 16) * AQROWB) + koff + laB;
                    uint32_t th[4];
                    ldsm_x4(th, sKH + rb);
                    mma_f16(s_[2 * nj2],     aq, th);
                    mma_f16(s_[2 * nj2 + 1], aq, th + 2);
                }
            }

            // ---- causal mask ----
            const int qrow0 = qbase + wid * 16 + (l >> 2);
            if (kbase + 63 > qbase + wid * 16) {
                #pragma unroll
                for (int nj = 0; nj < 8; nj++) {
                    int kp2 = kbase + nj * 8 + (l & 3) * 2;
                    if (kp2     > qrow0)     s_[nj][0] = -1e30f;
                    if (kp2 + 1 > qrow0)     s_[nj][1] = -1e30f;
                    if (kp2     > qrow0 + 8) s_[nj][2] = -1e30f;
                    if (kp2 + 1 > qrow0 + 8) s_[nj][3] = -1e30f;
                }
            }

            // ---- online softmax (exp2 domain) ----
            float mx0 = -1e30f, mx1 = -1e30f;
            #pragma unroll
            for (int nj = 0; nj < 8; nj++) {
                mx0 = fmaxf(mx0, fmaxf(s_[nj][0], s_[nj][1]));
                mx1 = fmaxf(mx1, fmaxf(s_[nj][2], s_[nj][3]));
            }
            mx0 = fmaxf(mx0, __shfl_xor_sync(0xffffffffu, mx0, 1));
            mx0 = fmaxf(mx0, __shfl_xor_sync(0xffffffffu, mx0, 2));
            mx1 = fmaxf(mx1, __shfl_xor_sync(0xffffffffu, mx1, 1));
            mx1 = fmaxf(mx1, __shfl_xor_sync(0xffffffffu, mx1, 2));
            float nm0 = fmaxf(rm0, mx0), nm1 = fmaxf(rm1, mx1);

            bool changed = (nm0 != rm0) | (nm1 != rm1);
            if (__any_sync(0xffffffffu, changed)) {
                float al0 = exp2f(rm0 - nm0), al1 = exp2f(rm1 - nm1);
                lp0 *= al0; lp1 *= al1;
                #pragma unroll
                for (int dj = 0; dj < 16; dj++) {
                    o[dj][0] *= al0; o[dj][1] *= al0;
                    o[dj][2] *= al1; o[dj][3] *= al1;
                }
                rm0 = nm0; rm1 = nm1;
            }

            float ps0 = 0.f, ps1 = 0.f;
            #pragma unroll
            for (int nj = 0; nj < 8; nj++) {
                s_[nj][0] = exp2f(s_[nj][0] - rm0);
                s_[nj][1] = exp2f(s_[nj][1] - rm0);
                s_[nj][2] = exp2f(s_[nj][2] - rm1);
                s_[nj][3] = exp2f(s_[nj][3] - rm1);
                ps0 += s_[nj][0] + s_[nj][1];
                ps1 += s_[nj][2] + s_[nj][3];
            }
            lp0 += ps0;
            lp1 += ps1;

            // ---- O += P V ----
            #pragma unroll
            for (int kks = 0; kks < 4; kks++) {
                uint32_t ap[4];
                {
                    const float* p0 = s_[2 * kks];
                    const float* p1 = s_[2 * kks + 1];
                    ap[0] = h2_as_u32(__floats2half2_rn(p0[0], p0[1]));
                    ap[1] = h2_as_u32(__floats2half2_rn(p0[2], p0[3]));
                    ap[2] = h2_as_u32(__floats2half2_rn(p1[0], p1[1]));
                    ap[3] = h2_as_u32(__floats2half2_rn(p1[2], p1[3]));
                }
                uint32_t rvb = (uint32_t)((kks * 16) * AQROWB) + laV;
                #pragma unroll
                for (int dj2 = 0; dj2 < 8; dj2++) {
                    uint32_t coff = dj2 * 32;
                    uint32_t tv[4];
                    ldsm_x4_t(tv, sVH + rvb + coff);
                    mma_f16(o[2 * dj2],     ap, tv);
                    mma_f16(o[2 * dj2 + 1], ap, tv + 2);
                }
            }
        }

        // ---- finalize this qtile ----
        lp0 += __shfl_xor_sync(0xffffffffu, lp0, 1);
        lp0 += __shfl_xor_sync(0xffffffffu, lp0, 2);
        lp1 += __shfl_xor_sync(0xffffffffu, lp1, 1);
        lp1 += __shfl_xor_sync(0xffffffffu, lp1, 2);
        float inv0 = 1.0f / lp0, inv1 = 1.0f / lp1;

        const size_t row0 = (size_t)(b * SEQ + qbase + wid * 16 + (l >> 2));
        const int colb = h * HDIM + (l & 3) * 2;
        #pragma unroll
        for (int dj = 0; dj < 16; dj++) {
            int col = colb + dj * 8;
            *(__half2*)(Yh + row0 * DMODEL + col) =
                __floats2half2_rn(o[dj][0] * inv0, o[dj][1] * inv0);
            *(__half2*)(Yh + (row0 + 8) * DMODEL + col) =
                __floats2half2_rn(o[dj][2] * inv1, o[dj][3] * inv1);
        }
    }
}

// ---------------------------------------------------------------------------
extern "C" void kernel_launch(void* const* d_in, const int* in_sizes, int n_in,
                              void* d_out, int out_size)
{
    (void)in_sizes; (void)n_in; (void)out_size;
    const float* x     = (const float*)d_in[0];
    const float* Wq    = (const float*)d_in[1];
    const float* Wkv   = (const float*)d_in[2];
    const float* Wproj = (const float*)d_in[3];
    float* out = (float*)d_out;

    __half *xh, *wh, *wph, *qkvh, *yh;
    cudaGetSymbolAddress((void**)&xh,   g_xh);
    cudaGetSymbolAddress((void**)&wh,   g_wh);
    cudaGetSymbolAddress((void**)&wph,  g_wph);
    cudaGetSymbolAddress((void**)&qkvh, g_qkvh);
    cudaGetSymbolAddress((void**)&yh,   g_yh);

    cudaFuncSetAttribute(gemm_mma<true>,  cudaFuncAttributeMaxDynamicSharedMemorySize, G_SMEM);
    cudaFuncSetAttribute(gemm_mma<false>, cudaFuncAttributeMaxDynamicSharedMemorySize, G_SMEM);
    cudaFuncSetAttribute(attn_mma, cudaFuncAttributeMaxDynamicSharedMemorySize, A_SMEM);

    // 0) all fp32->fp16 conversions in one launch (4 float4 per thread)
    cvt_all<<<(CVT_TOTAL + 1023) / 1024, 256>>>(x, Wq, Wkv, Wproj, xh, wh, wph);

    // 1) fused QKV = x [Wq;Wkv]^T  -> fp16 [4096, 3072]
    gemm_mma<true><<<dim3(QKVW / 128, MTOT / 128), 256, G_SMEM>>>(xh, wh, qkvh,
                                                                  MTOT, QKVW, DMODEL);

    // 2) in-place RoPE on q heads (0..15) and k heads (16..19, scale folded)
    {
        int total = MTOT * (NHEAD + NKV) * (HDIM / 2);
        rope16<<<(total + 255) / 256, 256>>>(qkvh, QKVW, NHEAD + NKV);
    }

    // 3) attention -> yh (fp16), balanced qtile pairs
    attn_mma<<<dim3(SEQ / 256, BATCH * NHEAD), 256, A_SMEM>>>(qkvh, yh);

    // 4) out = y Wproj^T (fp32)
    gemm_mma<false><<<dim3(DMODEL / 128, MTOT / 128), 256, G_SMEM>>>(yh, wph, out,
                                                                     MTOT, DMODEL, DMODEL);
}